// round 7
// baseline (speedup 1.0000x reference)
#include <cuda_runtime.h>
#include <cuda_bf16.h>
#include <cstdint>

#define NB   16
#define NIN  256
#define NPHI 256
#define NT   240
#define KH   131584            // 512*257 Hermitian half
#define BK   32
#define NCH  (KH / BK)         // 4112
#define KSP  37                // 32*37 = 1184 = 8*148 exact waves
#define NS   3
#define STG_SZ 47104           // A hi/lo 16384 + B hi/lo 30720
#define OFF_AL 8192
#define OFF_BH 16384
#define OFF_BL 31744
#define NTHR 768

// ---------------- device scratch (static; no allocation) ----------------
__device__ float2         g_W[NB * 512 * 512];
__device__ unsigned short g_G1[(size_t)NT * KH];     // G hi bf16, [t][kh]
__device__ unsigned short g_G2[(size_t)NT * KH];     // G lo bf16
__device__ float          g_Part[(size_t)KSP * 4096 * NT];

// ---------------- helpers ----------------
__device__ __forceinline__ uint32_t smem_u32(const void* p){
    uint32_t a; asm("{ .reg .u64 t; cvta.to.shared.u64 t, %1; cvt.u32.u64 %0, t; }":"=r"(a):"l"(p)); return a;
}
__device__ __forceinline__ void cp16(uint32_t dst, const void* src){
    asm volatile("cp.async.cg.shared.global [%0], [%1], 16;" :: "r"(dst), "l"(src) : "memory");
}
__device__ __forceinline__ void sts128(uint32_t a, uint32_t x, uint32_t y, uint32_t z, uint32_t w){
    asm volatile("st.shared.v4.b32 [%0], {%1,%2,%3,%4};" :: "r"(a), "r"(x), "r"(y), "r"(z), "r"(w) : "memory");
}
__device__ __forceinline__ void ldsm4(uint32_t* d, uint32_t a){
    asm volatile("ldmatrix.sync.aligned.m8n8.x4.shared.b16 {%0,%1,%2,%3}, [%4];"
        : "=r"(d[0]), "=r"(d[1]), "=r"(d[2]), "=r"(d[3]) : "r"(a));
}
__device__ __forceinline__ void mma16816(float* c, const uint32_t* a, const uint32_t* b){
    asm volatile("mma.sync.aligned.m16n8k16.row.col.f32.bf16.bf16.f32 "
        "{%0,%1,%2,%3}, {%4,%5,%6,%7}, {%8,%9}, {%0,%1,%2,%3};"
        : "+f"(c[0]), "+f"(c[1]), "+f"(c[2]), "+f"(c[3])
        : "r"(a[0]), "r"(a[1]), "r"(a[2]), "r"(a[3]), "r"(b[0]), "r"(b[1]));
}
__device__ __forceinline__ void bar_sync(int id){
    asm volatile("bar.sync %0, %1;" :: "r"(id), "n"(NTHR) : "memory");
}
__device__ __forceinline__ void bar_arrive(int id){
    asm volatile("bar.arrive %0, %1;" :: "r"(id), "n"(NTHR) : "memory");
}

// ---------------- 512-pt radix-2 FFT (validated) ----------------
__device__ __forceinline__ void fft512(float2* buf, int tid, float sign)
{
    #pragma unroll
    for (int s = 0; s < 9; s++) {
        int half = 1 << s;
        int pos  = tid & (half - 1);
        int i0   = ((tid >> s) << (s + 1)) + pos;
        int i1   = i0 + half;
        float ang = sign * 3.14159265358979323846f * (float)pos / (float)half;
        float sv, cv;
        sincosf(ang, &sv, &cv);
        __syncthreads();
        float2 x0 = buf[i0], x1 = buf[i1];
        float tr = x1.x * cv - x1.y * sv;
        float ti = x1.x * sv + x1.y * cv;
        buf[i0] = make_float2(x0.x + tr, x0.y + ti);
        buf[i1] = make_float2(x0.x - tr, x0.y - ti);
    }
    __syncthreads();
}

__global__ void fft_rows_kernel(const float* __restrict__ f)
{
    int a = blockIdx.x, bb = blockIdx.y, tid = threadIdx.x;
    float2* wrow = g_W + ((size_t)bb << 18) + ((size_t)a << 9);
    if (a < 128 || a >= 384) {
        for (int i = tid; i < 512; i += 256) wrow[i] = make_float2(0.f, 0.f);
        return;
    }
    __shared__ float2 buf[512];
    const float* frow = f + (size_t)bb * (NIN * NIN) + (size_t)(a - 128) * NIN;
    for (int i = tid; i < 512; i += 256) {
        float v = (i >= 128 && i < 384) ? frow[i - 128] : 0.f;
        buf[__brev((unsigned)i) >> 23] = make_float2(v, 0.f);
    }
    fft512(buf, tid, -1.0f);
    for (int i = tid; i < 512; i += 256) wrow[i] = buf[i];
}

__global__ void fft_cols_kernel()
{
    int c = blockIdx.x, bb = blockIdx.y, tid = threadIdx.x;
    float2* base = g_W + ((size_t)bb << 18) + c;
    __shared__ float2 buf[512];
    for (int i = tid; i < 512; i += 256)
        buf[__brev((unsigned)i) >> 23] = base[(size_t)i << 9];
    fft512(buf, tid, -1.0f);
    for (int i = tid; i < 512; i += 256) base[(size_t)i << 9] = buf[i];
}

// ---------------- G tables: bf16 hi/lo split, [t][kh] ----------------
__global__ void ggen_kernel(const float* __restrict__ fil)
{
    int kh = blockIdx.x * 256 + threadIdx.x;
    if (kh >= KH) return;
    unsigned a = (unsigned)kh / 257u;
    unsigned b = (unsigned)kh - a * 257u;
    float c2 = 2.0f - 4.0f * fil[a * 512u + b];
    float w  = (b == 0u || b == 256u) ? 1.0f : 2.0f;
    float scale = w * (1.0f / 262144.0f);
    float gp = scale;
    float gc = (c2 - 1.0f) * scale;
    #pragma unroll 4
    for (int t = 0; t < NT; t++) {
        unsigned hb = __float_as_uint(gc) & 0xffff0000u;
        float lo = gc - __uint_as_float(hb);
        g_G1[(size_t)t * KH + kh] = (unsigned short)(hb >> 16);
        __nv_bfloat16 lb = __float2bfloat16(lo);
        g_G2[(size_t)t * KH + kh] = *reinterpret_cast<unsigned short*>(&lb);
        float gn = c2 * gc - gp;
        gp = gc; gc = gn;
    }
}

// ---------------- warp-specialized HMMA GEMM ----------------
// 768 thr: warps 0-19 consumers (4m x 5n, n=48 each), warps 20-23 producers.
// Named barriers: full[s]=1+s (producer arrive, consumer sync),
//                 empty[s]=4+s (consumer arrive, producer sync).
__global__ void __launch_bounds__(NTHR, 1)
gemm_kernel(const int* __restrict__ idx0, const int* __restrict__ idx1)
{
    extern __shared__ char smem[];
    const uint32_t sb = smem_u32(smem);
    const int tid = threadIdx.x;
    const int wid = tid >> 5, lane = tid & 31;
    const int mt = blockIdx.x;       // 0..31
    const int ks = blockIdx.y;       // 0..36
    const int bb = mt >> 1;
    const int c0 = (ks * NCH) / KSP, c1 = ((ks + 1) * NCH) / KSP;

    if (wid >= 20) {
        // ================= PRODUCER (4 warps, 128 threads) =================
        const int r = tid - 640;                 // row 0..127
        const int p = ((mt & 1) << 7) + r;
        const int x = idx0[p], y = idx1[p];
        const float TH = 6.2831853071795864769e+00f / 512.0f;
        float cy, sy; sincosf((float)(((unsigned)y) & 511u) * TH, &sy, &cy);
        int wd = (x - 256 * y) % 512; if (wd < 0) wd += 512;
        float cw, sw_; sincosf((float)wd * TH, &sw_, &cw);
        const float2* Wb = g_W + ((size_t)bb << 18);
        const uint32_t rsw = ((uint32_t)r >> 1) & 3u;

        for (int c = c0; c < c1; c++) {
            const int s = c % 3;
            if (c >= c0 + NS) bar_sync(4 + s);
            const uint32_t st = sb + (uint32_t)s * STG_SZ;
            const int k0 = c * BK;

            // B hi/lo via cp.async: 1920 16B chunks over 128 threads
            #pragma unroll
            for (int ii = 0; ii < 15; ii++) {
                int i = r + ii * 128;
                int half = i >= 960;
                int j = i - (half ? 960 : 0);
                int n = j >> 2, cc = j & 3;
                uint32_t d = st + (half ? OFF_BL : OFF_BH) + (uint32_t)n * 64u
                           + ((((uint32_t)cc) ^ (((uint32_t)n >> 1) & 3u)) << 4);
                const unsigned short* src = (half ? g_G2 : g_G1) + (size_t)n * KH + k0 + cc * 8;
                cp16(d, src);
            }
            asm volatile("cp.async.commit_group;" ::: "memory");

            // A-gen: 32 k-elems for row r (exact int phase + rotation)
            {
                unsigned a0 = (unsigned)k0 / 257u;
                unsigned b  = (unsigned)k0 - a0 * 257u;
                unsigned off = (a0 << 9) + b;
                unsigned ph = (a0 * (unsigned)x + b * (unsigned)y) & 511u;
                float cr, ci; __sincosf((float)ph * TH, &ci, &cr);
                #pragma unroll
                for (int q = 0; q < 4; q++) {
                    uint32_t hp[4], lp[4];
                    float m0 = 0.f;
                    #pragma unroll
                    for (int e = 0; e < 8; e++) {
                        float2 w = Wb[off];
                        float mv = fmaf(w.x, cr, -w.y * ci);
                        if ((e & 1) == 0) m0 = mv;
                        else {
                            unsigned h0 = __float_as_uint(m0) & 0xffff0000u;
                            unsigned h1 = __float_as_uint(mv) & 0xffff0000u;
                            hp[e >> 1] = __byte_perm(h0, h1, 0x7632);
                            float l0 = m0 - __uint_as_float(h0);
                            float l1 = mv - __uint_as_float(h1);
                            asm("cvt.rn.bf16x2.f32 %0, %1, %2;" : "=r"(lp[e >> 1]) : "f"(l1), "f"(l0));
                        }
                        bool wrap = (b == 256u);
                        float fc = wrap ? cw : cy, fs = wrap ? sw_ : sy;
                        float nr = cr * fc - ci * fs;
                        float ni = fmaf(cr, fs, ci * fc);
                        cr = nr; ci = ni;
                        off += wrap ? 256u : 1u;
                        b = wrap ? 0u : b + 1u;
                    }
                    uint32_t da = st + (uint32_t)r * 64u + ((((uint32_t)q) ^ rsw) << 4);
                    sts128(da, hp[0], hp[1], hp[2], hp[3]);
                    sts128(da + OFF_AL, lp[0], lp[1], lp[2], lp[3]);
                }
            }
            asm volatile("cp.async.wait_group 0;" ::: "memory");
            bar_arrive(1 + s);
        }
    } else {
        // ================= CONSUMER (20 warps = 4m x 5n, n=48) =================
        const int wm = wid & 3, wn = wid >> 2;       // wn 0..4
        const int mrow0 = wm * 32;
        const int n0 = wn * 48;                       // 5 x 48 = 240
        const int lrowA = (lane & 7) + ((lane >> 3) & 1) * 8;
        const int lchA  = lane >> 4;
        const int lrowB = (lane & 7) + (lane >> 4) * 8;
        const int lchB  = (lane >> 3) & 1;

        float acc[2][6][4];
        #pragma unroll
        for (int s = 0; s < 2; s++)
            #pragma unroll
            for (int t8 = 0; t8 < 6; t8++)
                #pragma unroll
                for (int q = 0; q < 4; q++) acc[s][t8][q] = 0.f;

        for (int c = c0; c < c1; c++) {
            const int s3 = c % 3;
            bar_sync(1 + s3);
            const uint32_t st = sb + (uint32_t)s3 * STG_SZ;
            #pragma unroll
            for (int ks2 = 0; ks2 < 2; ks2++) {
                uint32_t Ah[2][4], Al[2][4];
                #pragma unroll
                for (int s = 0; s < 2; s++) {
                    int row = mrow0 + s * 16 + lrowA;
                    uint32_t sw4 = (uint32_t)((row >> 1) & 3);
                    uint32_t a1 = st + (uint32_t)row * 64u
                                + ((((uint32_t)(ks2 * 2 + lchA)) ^ sw4) << 4);
                    ldsm4(Ah[s], a1);
                    ldsm4(Al[s], a1 + OFF_AL);
                }
                #pragma unroll
                for (int jp = 0; jp < 3; jp++) {
                    int nr_ = n0 + jp * 16 + lrowB;
                    uint32_t sw4 = (uint32_t)((nr_ >> 1) & 3);
                    uint32_t ba = st + OFF_BH + (uint32_t)nr_ * 64u
                                + ((((uint32_t)(ks2 * 2 + lchB)) ^ sw4) << 4);
                    uint32_t Bh[4], Bl[4];
                    ldsm4(Bh, ba);
                    ldsm4(Bl, ba + (OFF_BL - OFF_BH));
                    // acc reuse distance 4 throughout
                    mma16816(acc[0][2 * jp],     Ah[0], Bh);
                    mma16816(acc[0][2 * jp + 1], Ah[0], Bh + 2);
                    mma16816(acc[1][2 * jp],     Ah[1], Bh);
                    mma16816(acc[1][2 * jp + 1], Ah[1], Bh + 2);
                    mma16816(acc[0][2 * jp],     Al[0], Bh);
                    mma16816(acc[0][2 * jp + 1], Al[0], Bh + 2);
                    mma16816(acc[1][2 * jp],     Al[1], Bh);
                    mma16816(acc[1][2 * jp + 1], Al[1], Bh + 2);
                    mma16816(acc[0][2 * jp],     Ah[0], Bl);
                    mma16816(acc[0][2 * jp + 1], Ah[0], Bl + 2);
                    mma16816(acc[1][2 * jp],     Ah[1], Bl);
                    mma16816(acc[1][2 * jp + 1], Ah[1], Bl + 2);
                }
            }
            bar_arrive(4 + s3);
        }

        // epilogue: write partials
        const int gq = lane >> 2, tg = lane & 3;
        #pragma unroll
        for (int s = 0; s < 2; s++) {
            const int rbase = mt * 128 + mrow0 + s * 16 + gq;
            #pragma unroll
            for (int t8 = 0; t8 < 6; t8++) {
                const int tt = n0 + t8 * 8 + tg * 2;
                float* d0 = g_Part + ((size_t)ks * 4096 + rbase) * NT + tt;
                *(float2*)d0 = make_float2(acc[s][t8][0], acc[s][t8][1]);
                float* d1 = d0 + 8 * NT;
                *(float2*)d1 = make_float2(acc[s][t8][2], acc[s][t8][3]);
            }
        }
    }
}

// ---------------- reduce over k-splits ----------------
__global__ void reduce_kernel(float* __restrict__ out)
{
    int i = blockIdx.x * 256 + threadIdx.x;   // i = row*240 + t
    if (i >= 4096 * NT) return;
    float s = 0.f;
    #pragma unroll
    for (int k = 0; k < KSP; k++) s += g_Part[(size_t)k * (4096 * NT) + i];
    out[i] = s;
}

extern "C" void kernel_launch(void* const* d_in, const int* in_sizes, int n_in,
                              void* d_out, int out_size)
{
    const float* f   = (const float*)d_in[0];
    const float* fil = (const float*)d_in[1];
    const int*  idx0 = (const int*)d_in[2];
    const int*  idx1 = (const int*)d_in[3];
    float* out = (float*)d_out;

    cudaFuncSetAttribute(gemm_kernel, cudaFuncAttributeMaxDynamicSharedMemorySize, NS * STG_SZ);

    fft_rows_kernel<<<dim3(512, NB), 256>>>(f);
    fft_cols_kernel<<<dim3(512, NB), 256>>>();
    ggen_kernel<<<(KH + 255) / 256, 256>>>(fil);
    gemm_kernel<<<dim3(32, KSP), NTHR, NS * STG_SZ>>>(idx0, idx1);
    reduce_kernel<<<(4096 * NT + 255) / 256, 256>>>(out);
}

// round 8
// speedup vs baseline: 1.6246x; 1.6246x over previous
#include <cuda_runtime.h>
#include <cuda_fp16.h>
#include <cuda_bf16.h>
#include <cstdint>

#define NB   16
#define NIN  256
#define NPHI 256
#define NT   240
#define KH   131584            // 512*257 Hermitian half
#define BK   32
#define NCH  (KH / BK)         // 4112
#define KSP  37                // 32*37 = 1184 = 8*148 exact waves
#define NS   3
#define STG_SZ 31744           // A hi/lo 16384 + B 15360
#define OFF_AL 8192
#define OFF_BH 16384

// ---------------- device scratch (static; no allocation) ----------------
__device__ float2         g_W[NB * 512 * 512];
__device__ unsigned short g_G1[(size_t)NT * KH];     // G fp16 (g * 2^-8), [t][kh]
__device__ float          g_Part[(size_t)KSP * 4096 * NT];

// ---------------- helpers ----------------
__device__ __forceinline__ uint32_t smem_u32(const void* p){
    uint32_t a; asm("{ .reg .u64 t; cvta.to.shared.u64 t, %1; cvt.u32.u64 %0, t; }":"=r"(a):"l"(p)); return a;
}
__device__ __forceinline__ void cp16(uint32_t dst, const void* src){
    asm volatile("cp.async.cg.shared.global [%0], [%1], 16;" :: "r"(dst), "l"(src) : "memory");
}
__device__ __forceinline__ void sts128(uint32_t a, uint32_t x, uint32_t y, uint32_t z, uint32_t w){
    asm volatile("st.shared.v4.b32 [%0], {%1,%2,%3,%4};" :: "r"(a), "r"(x), "r"(y), "r"(z), "r"(w) : "memory");
}
__device__ __forceinline__ void ldsm4(uint32_t* d, uint32_t a){
    asm volatile("ldmatrix.sync.aligned.m8n8.x4.shared.b16 {%0,%1,%2,%3}, [%4];"
        : "=r"(d[0]), "=r"(d[1]), "=r"(d[2]), "=r"(d[3]) : "r"(a));
}
__device__ __forceinline__ void mma16816h(float* c, const uint32_t* a, const uint32_t* b){
    asm volatile("mma.sync.aligned.m16n8k16.row.col.f32.f16.f16.f32 "
        "{%0,%1,%2,%3}, {%4,%5,%6,%7}, {%8,%9}, {%0,%1,%2,%3};"
        : "+f"(c[0]), "+f"(c[1]), "+f"(c[2]), "+f"(c[3])
        : "r"(a[0]), "r"(a[1]), "r"(a[2]), "r"(a[3]), "r"(b[0]), "r"(b[1]));
}
__device__ __forceinline__ void bar_sync(int id){
    asm volatile("bar.sync %0, 512;" :: "r"(id) : "memory");
}
__device__ __forceinline__ void bar_arrive(int id){
    asm volatile("bar.arrive %0, 512;" :: "r"(id) : "memory");
}

// ---------------- 512-pt radix-2 FFT (validated) ----------------
__device__ __forceinline__ void fft512(float2* buf, int tid, float sign)
{
    #pragma unroll
    for (int s = 0; s < 9; s++) {
        int half = 1 << s;
        int pos  = tid & (half - 1);
        int i0   = ((tid >> s) << (s + 1)) + pos;
        int i1   = i0 + half;
        float ang = sign * 3.14159265358979323846f * (float)pos / (float)half;
        float sv, cv;
        sincosf(ang, &sv, &cv);
        __syncthreads();
        float2 x0 = buf[i0], x1 = buf[i1];
        float tr = x1.x * cv - x1.y * sv;
        float ti = x1.x * sv + x1.y * cv;
        buf[i0] = make_float2(x0.x + tr, x0.y + ti);
        buf[i1] = make_float2(x0.x - tr, x0.y - ti);
    }
    __syncthreads();
}

__global__ void fft_rows_kernel(const float* __restrict__ f)
{
    int a = blockIdx.x, bb = blockIdx.y, tid = threadIdx.x;
    float2* wrow = g_W + ((size_t)bb << 18) + ((size_t)a << 9);
    if (a < 128 || a >= 384) {
        for (int i = tid; i < 512; i += 256) wrow[i] = make_float2(0.f, 0.f);
        return;
    }
    __shared__ float2 buf[512];
    const float* frow = f + (size_t)bb * (NIN * NIN) + (size_t)(a - 128) * NIN;
    for (int i = tid; i < 512; i += 256) {
        float v = (i >= 128 && i < 384) ? frow[i - 128] : 0.f;
        buf[__brev((unsigned)i) >> 23] = make_float2(v, 0.f);
    }
    fft512(buf, tid, -1.0f);
    for (int i = tid; i < 512; i += 256) wrow[i] = buf[i];
}

__global__ void fft_cols_kernel()
{
    int c = blockIdx.x, bb = blockIdx.y, tid = threadIdx.x;
    float2* base = g_W + ((size_t)bb << 18) + c;
    __shared__ float2 buf[512];
    for (int i = tid; i < 512; i += 256)
        buf[__brev((unsigned)i) >> 23] = base[(size_t)i << 9];
    fft512(buf, tid, -1.0f);
    for (int i = tid; i < 512; i += 256) base[(size_t)i << 9] = buf[i];
}

// ---------------- G table: fp16(g_{t+1} * 2^-8), [t][kh] ----------------
// Weight and 1/N^2 are folded into A.
__global__ void ggen_kernel(const float* __restrict__ fil)
{
    int kh = blockIdx.x * 256 + threadIdx.x;
    if (kh >= KH) return;
    unsigned a = (unsigned)kh / 257u;
    unsigned b = (unsigned)kh - a * 257u;
    float c2 = 2.0f - 4.0f * fil[a * 512u + b];
    const float s8 = 0.00390625f;              // 2^-8
    float gp = s8;                              // g_0 * 2^-8
    float gc = (c2 - 1.0f) * s8;                // g_1 * 2^-8
    #pragma unroll 4
    for (int t = 0; t < NT; t++) {
        __half h = __float2half_rn(gc);
        g_G1[(size_t)t * KH + kh] = *reinterpret_cast<unsigned short*>(&h);
        float gn = c2 * gc - gp;
        gp = gc; gc = gn;
    }
}

// ---------------- warp-specialized HMMA GEMM (fp16 2-pass) ----------------
// 512 thr: warps 0-11 consumers (4m x 3n, n=80 each), warps 12-15 producers.
__global__ void __launch_bounds__(512, 1)
gemm_kernel(const int* __restrict__ idx0, const int* __restrict__ idx1)
{
    extern __shared__ char smem[];
    const uint32_t sb = smem_u32(smem);
    const int tid = threadIdx.x;
    const int wid = tid >> 5, lane = tid & 31;
    const int mt = blockIdx.x;       // 0..31
    const int ks = blockIdx.y;       // 0..36
    const int bb = mt >> 1;
    const int c0 = (ks * NCH) / KSP, c1 = ((ks + 1) * NCH) / KSP;

    if (wid >= 12) {
        // ================= PRODUCER (4 warps, 128 threads) =================
        const int r = tid - 384;                 // row 0..127
        const int p = ((mt & 1) << 7) + r;
        const int x = idx0[p], y = idx1[p];
        const float TH = 6.2831853071795864769e+00f / 512.0f;
        float cy, sy; sincosf((float)(((unsigned)y) & 511u) * TH, &sy, &cy);
        int wd = (x - 256 * y) % 512; if (wd < 0) wd += 512;
        float cw, sw_; sincosf((float)wd * TH, &sw_, &cw);
        const float2* Wb = g_W + ((size_t)bb << 18);
        const uint32_t rsw = ((uint32_t)r >> 1) & 3u;

        for (int c = c0; c < c1; c++) {
            const int s = c % 3;
            if (c >= c0 + NS) bar_sync(4 + s);
            const uint32_t st = sb + (uint32_t)s * STG_SZ;
            const int k0 = c * BK;

            // B via cp.async: 960 16B chunks over 128 threads (7.5 rounds)
            #pragma unroll
            for (int ii = 0; ii < 8; ii++) {
                int i = r + ii * 128;
                if (i < 960) {
                    int n = i >> 2, cc = i & 3;
                    uint32_t d = st + OFF_BH + (uint32_t)n * 64u
                               + ((((uint32_t)cc) ^ (((uint32_t)n >> 1) & 3u)) << 4);
                    cp16(d, g_G1 + (size_t)n * KH + k0 + cc * 8);
                }
            }
            asm volatile("cp.async.commit_group;" ::: "memory");

            // A-gen: 32 k-elems for row r (exact int phase + rotation),
            // weight * 2^-10 folded in; fp16 hi + residual lo.
            {
                unsigned a0 = (unsigned)k0 / 257u;
                unsigned b  = (unsigned)k0 - a0 * 257u;
                unsigned off = (a0 << 9) + b;
                unsigned ph = (a0 * (unsigned)x + b * (unsigned)y) & 511u;
                float cr, ci; __sincosf((float)ph * TH, &ci, &cr);
                #pragma unroll
                for (int q = 0; q < 4; q++) {
                    uint32_t hp[4], lp[4];
                    float m0 = 0.f;
                    #pragma unroll
                    for (int e = 0; e < 8; e++) {
                        float2 w = Wb[off];
                        float wsc = (b == 0u || b == 256u) ? 9.765625e-4f : 1.953125e-3f;
                        float mv = fmaf(w.x, cr, -w.y * ci) * wsc;
                        if ((e & 1) == 0) m0 = mv;
                        else {
                            __half h0 = __float2half_rn(m0);
                            __half h1 = __float2half_rn(mv);
                            float l0 = m0 - __half2float(h0);
                            float l1 = mv - __half2float(h1);
                            __half2 hh = __halves2half2(h0, h1);
                            __half2 ll = __halves2half2(__float2half_rn(l0), __float2half_rn(l1));
                            hp[e >> 1] = *reinterpret_cast<uint32_t*>(&hh);
                            lp[e >> 1] = *reinterpret_cast<uint32_t*>(&ll);
                        }
                        bool wrap = (b == 256u);
                        float fc = wrap ? cw : cy, fs = wrap ? sw_ : sy;
                        float nr = cr * fc - ci * fs;
                        float ni = fmaf(cr, fs, ci * fc);
                        cr = nr; ci = ni;
                        off += wrap ? 256u : 1u;
                        b = wrap ? 0u : b + 1u;
                    }
                    uint32_t da = st + (uint32_t)r * 64u + ((((uint32_t)q) ^ rsw) << 4);
                    sts128(da, hp[0], hp[1], hp[2], hp[3]);
                    sts128(da + OFF_AL, lp[0], lp[1], lp[2], lp[3]);
                }
            }
            asm volatile("cp.async.wait_group 0;" ::: "memory");
            bar_arrive(1 + s);
        }
    } else {
        // ================= CONSUMER (12 warps = 4m x 3n, n=80) =================
        const int wm = wid & 3, wn = wid >> 2;       // wn 0..2
        const int mrow0 = wm * 32;
        const int n0 = wn * 80;
        const int lrowA = (lane & 7) + ((lane >> 3) & 1) * 8;
        const int lchA  = lane >> 4;
        const int lrowB = (lane & 7) + (lane >> 4) * 8;
        const int lchB  = (lane >> 3) & 1;

        float acc[2][10][4];
        #pragma unroll
        for (int s = 0; s < 2; s++)
            #pragma unroll
            for (int t8 = 0; t8 < 10; t8++)
                #pragma unroll
                for (int q = 0; q < 4; q++) acc[s][t8][q] = 0.f;

        for (int c = c0; c < c1; c++) {
            const int s3 = c % 3;
            bar_sync(1 + s3);
            const uint32_t st = sb + (uint32_t)s3 * STG_SZ;
            #pragma unroll
            for (int ks2 = 0; ks2 < 2; ks2++) {
                uint32_t Ah[2][4], Al[2][4];
                #pragma unroll
                for (int s = 0; s < 2; s++) {
                    int row = mrow0 + s * 16 + lrowA;
                    uint32_t sw4 = (uint32_t)((row >> 1) & 3);
                    uint32_t a1 = st + (uint32_t)row * 64u
                                + ((((uint32_t)(ks2 * 2 + lchA)) ^ sw4) << 4);
                    ldsm4(Ah[s], a1);
                    ldsm4(Al[s], a1 + OFF_AL);
                }
                #pragma unroll
                for (int jp = 0; jp < 5; jp++) {
                    int nr_ = n0 + jp * 16 + lrowB;
                    uint32_t sw4 = (uint32_t)((nr_ >> 1) & 3);
                    uint32_t ba = st + OFF_BH + (uint32_t)nr_ * 64u
                                + ((((uint32_t)(ks2 * 2 + lchB)) ^ sw4) << 4);
                    uint32_t Bh[4];
                    ldsm4(Bh, ba);
                    // acc reuse distance 4
                    mma16816h(acc[0][2 * jp],     Ah[0], Bh);
                    mma16816h(acc[0][2 * jp + 1], Ah[0], Bh + 2);
                    mma16816h(acc[1][2 * jp],     Ah[1], Bh);
                    mma16816h(acc[1][2 * jp + 1], Ah[1], Bh + 2);
                    mma16816h(acc[0][2 * jp],     Al[0], Bh);
                    mma16816h(acc[0][2 * jp + 1], Al[0], Bh + 2);
                    mma16816h(acc[1][2 * jp],     Al[1], Bh);
                    mma16816h(acc[1][2 * jp + 1], Al[1], Bh + 2);
                }
            }
            bar_arrive(4 + s3);
        }

        // epilogue: write partials
        const int gq = lane >> 2, tg = lane & 3;
        #pragma unroll
        for (int s = 0; s < 2; s++) {
            const int rbase = mt * 128 + mrow0 + s * 16 + gq;
            #pragma unroll
            for (int t8 = 0; t8 < 10; t8++) {
                const int tt = n0 + t8 * 8 + tg * 2;
                float* d0 = g_Part + ((size_t)ks * 4096 + rbase) * NT + tt;
                *(float2*)d0 = make_float2(acc[s][t8][0], acc[s][t8][1]);
                float* d1 = d0 + 8 * NT;
                *(float2*)d1 = make_float2(acc[s][t8][2], acc[s][t8][3]);
            }
        }
    }
}

// ---------------- reduce over k-splits ----------------
__global__ void reduce_kernel(float* __restrict__ out)
{
    int i = blockIdx.x * 256 + threadIdx.x;   // i = row*240 + t
    if (i >= 4096 * NT) return;
    float s = 0.f;
    #pragma unroll
    for (int k = 0; k < KSP; k++) s += g_Part[(size_t)k * (4096 * NT) + i];
    out[i] = s;
}

extern "C" void kernel_launch(void* const* d_in, const int* in_sizes, int n_in,
                              void* d_out, int out_size)
{
    const float* f   = (const float*)d_in[0];
    const float* fil = (const float*)d_in[1];
    const int*  idx0 = (const int*)d_in[2];
    const int*  idx1 = (const int*)d_in[3];
    float* out = (float*)d_out;

    cudaFuncSetAttribute(gemm_kernel, cudaFuncAttributeMaxDynamicSharedMemorySize, NS * STG_SZ);

    fft_rows_kernel<<<dim3(512, NB), 256>>>(f);
    fft_cols_kernel<<<dim3(512, NB), 256>>>();
    ggen_kernel<<<(KH + 255) / 256, 256>>>(fil);
    gemm_kernel<<<dim3(32, KSP), 512, NS * STG_SZ>>>(idx0, idx1);
    reduce_kernel<<<(4096 * NT + 255) / 256, 256>>>(out);
}

// round 9
// speedup vs baseline: 1.6580x; 1.0206x over previous
#include <cuda_runtime.h>
#include <cuda_fp16.h>
#include <cuda_bf16.h>
#include <cstdint>

#define NB   16
#define NIN  256
#define NPHI 256
#define NT   240
#define KH   131584            // 512*257 Hermitian half
#define BK   64
#define NCH  (KH / BK)         // 2056
#define KSP  37                // 32*37 = 1184 = 8*148 exact waves
#define NS   3
#define OFF_AL 16384
#define OFF_B  32768
#define STG_SZ 63488           // A hi/lo 32KB + B 30KB
#define SMEM_TOT (NS * STG_SZ)

// ---------------- device scratch (static; no allocation) ----------------
__device__ float2         g_W[NB * 512 * 512];
__device__ unsigned short g_G1[(size_t)NT * KH];     // G fp16 (g * 2^-8), [t][kh]
__device__ float          g_Part[(size_t)KSP * 4096 * NT];

// ---------------- helpers ----------------
__device__ __forceinline__ uint32_t smem_u32(const void* p){
    uint32_t a; asm("{ .reg .u64 t; cvta.to.shared.u64 t, %1; cvt.u32.u64 %0, t; }":"=r"(a):"l"(p)); return a;
}
__device__ __forceinline__ void cp16(uint32_t dst, const void* src){
    asm volatile("cp.async.cg.shared.global [%0], [%1], 16;" :: "r"(dst), "l"(src) : "memory");
}
__device__ __forceinline__ void sts128(uint32_t a, uint32_t x, uint32_t y, uint32_t z, uint32_t w){
    asm volatile("st.shared.v4.b32 [%0], {%1,%2,%3,%4};" :: "r"(a), "r"(x), "r"(y), "r"(z), "r"(w) : "memory");
}
__device__ __forceinline__ void ldsm4(uint32_t* d, uint32_t a){
    asm volatile("ldmatrix.sync.aligned.m8n8.x4.shared.b16 {%0,%1,%2,%3}, [%4];"
        : "=r"(d[0]), "=r"(d[1]), "=r"(d[2]), "=r"(d[3]) : "r"(a));
}
__device__ __forceinline__ void mma16816h(float* c, const uint32_t* a, const uint32_t* b){
    asm volatile("mma.sync.aligned.m16n8k16.row.col.f32.f16.f16.f32 "
        "{%0,%1,%2,%3}, {%4,%5,%6,%7}, {%8,%9}, {%0,%1,%2,%3};"
        : "+f"(c[0]), "+f"(c[1]), "+f"(c[2]), "+f"(c[3])
        : "r"(a[0]), "r"(a[1]), "r"(a[2]), "r"(a[3]), "r"(b[0]), "r"(b[1]));
}
__device__ __forceinline__ void bar_sync(int id){
    asm volatile("bar.sync %0, 512;" :: "r"(id) : "memory");
}
__device__ __forceinline__ void bar_arrive(int id){
    asm volatile("bar.arrive %0, 512;" :: "r"(id) : "memory");
}

// ---------------- 512-pt radix-2 FFT (validated) ----------------
__device__ __forceinline__ void fft512(float2* buf, int tid, float sign)
{
    #pragma unroll
    for (int s = 0; s < 9; s++) {
        int half = 1 << s;
        int pos  = tid & (half - 1);
        int i0   = ((tid >> s) << (s + 1)) + pos;
        int i1   = i0 + half;
        float ang = sign * 3.14159265358979323846f * (float)pos / (float)half;
        float sv, cv;
        sincosf(ang, &sv, &cv);
        __syncthreads();
        float2 x0 = buf[i0], x1 = buf[i1];
        float tr = x1.x * cv - x1.y * sv;
        float ti = x1.x * sv + x1.y * cv;
        buf[i0] = make_float2(x0.x + tr, x0.y + ti);
        buf[i1] = make_float2(x0.x - tr, x0.y - ti);
    }
    __syncthreads();
}

__global__ void fft_rows_kernel(const float* __restrict__ f)
{
    int a = blockIdx.x, bb = blockIdx.y, tid = threadIdx.x;
    float2* wrow = g_W + ((size_t)bb << 18) + ((size_t)a << 9);
    if (a < 128 || a >= 384) {
        for (int i = tid; i < 512; i += 256) wrow[i] = make_float2(0.f, 0.f);
        return;
    }
    __shared__ float2 buf[512];
    const float* frow = f + (size_t)bb * (NIN * NIN) + (size_t)(a - 128) * NIN;
    for (int i = tid; i < 512; i += 256) {
        float v = (i >= 128 && i < 384) ? frow[i - 128] : 0.f;
        buf[__brev((unsigned)i) >> 23] = make_float2(v, 0.f);
    }
    fft512(buf, tid, -1.0f);
    for (int i = tid; i < 512; i += 256) wrow[i] = buf[i];
}

__global__ void fft_cols_kernel()
{
    int c = blockIdx.x, bb = blockIdx.y, tid = threadIdx.x;
    float2* base = g_W + ((size_t)bb << 18) + c;
    __shared__ float2 buf[512];
    for (int i = tid; i < 512; i += 256)
        buf[__brev((unsigned)i) >> 23] = base[(size_t)i << 9];
    fft512(buf, tid, -1.0f);
    for (int i = tid; i < 512; i += 256) base[(size_t)i << 9] = buf[i];
}

// ---------------- G table: fp16(g_{t+1} * 2^-8), [t][kh] ----------------
__global__ void ggen_kernel(const float* __restrict__ fil)
{
    int kh = blockIdx.x * 256 + threadIdx.x;
    if (kh >= KH) return;
    unsigned a = (unsigned)kh / 257u;
    unsigned b = (unsigned)kh - a * 257u;
    float c2 = 2.0f - 4.0f * fil[a * 512u + b];
    const float s8 = 0.00390625f;              // 2^-8
    float gp = s8;
    float gc = (c2 - 1.0f) * s8;
    #pragma unroll 4
    for (int t = 0; t < NT; t++) {
        __half h = __float2half_rn(gc);
        g_G1[(size_t)t * KH + kh] = *reinterpret_cast<unsigned short*>(&h);
        float gn = c2 * gc - gp;
        gp = gc; gc = gn;
    }
}

// ---------------- warp-specialized HMMA GEMM (fp16 2-pass, BK=64) ----------------
// 512 thr: warps 0-11 consumers (4m x 3n, n=80 each), warps 12-15 producers.
// Stage: A hi [128][64]fp16 + A lo + B [240][64]fp16, 128B rows,
// swizzle: 16B-chunk index ^ (row & 7).
__global__ void __launch_bounds__(512, 1)
gemm_kernel(const int* __restrict__ idx0, const int* __restrict__ idx1)
{
    extern __shared__ char smem[];
    const uint32_t sb = smem_u32(smem);
    const int tid = threadIdx.x;
    const int wid = tid >> 5, lane = tid & 31;
    const int mt = blockIdx.x;       // 0..31
    const int ks = blockIdx.y;       // 0..36
    const int bb = mt >> 1;
    const int c0 = (ks * NCH) / KSP, c1 = ((ks + 1) * NCH) / KSP;

    if (wid >= 12) {
        // ================= PRODUCER (4 warps, 128 threads) =================
        const int r = tid - 384;                 // row 0..127
        const int p = ((mt & 1) << 7) + r;
        const int x = idx0[p], y = idx1[p];
        const float TH = 6.2831853071795864769e+00f / 512.0f;
        float cy, sy; sincosf((float)(((unsigned)y) & 511u) * TH, &sy, &cy);
        int wd = (x - 256 * y) % 512; if (wd < 0) wd += 512;
        float cw, sw_; sincosf((float)wd * TH, &sw_, &cw);
        const float2* Wb = g_W + ((size_t)bb << 18);
        const uint32_t rx = (uint32_t)r & 7u;

        for (int c = c0; c < c1; c++) {
            const int s = c % 3;
            if (c >= c0 + NS) bar_sync(4 + s);
            const uint32_t st = sb + (uint32_t)s * STG_SZ;
            const int k0 = c * BK;

            // B via cp.async: 1920 16B chunks over 128 threads (15 rounds)
            #pragma unroll
            for (int ii = 0; ii < 15; ii++) {
                int i = r + ii * 128;
                int n = i >> 3, cc = i & 7;
                uint32_t d = st + OFF_B + (uint32_t)n * 128u
                           + ((((uint32_t)cc) ^ ((uint32_t)n & 7u)) << 4);
                cp16(d, g_G1 + (size_t)n * KH + k0 + cc * 8);
            }
            asm volatile("cp.async.commit_group;" ::: "memory");

            // A-gen: 64 k-elems for row r; weight*2^-10 folded; fp16 hi + lo.
            {
                unsigned a0 = (unsigned)k0 / 257u;
                unsigned b  = (unsigned)k0 - a0 * 257u;
                unsigned off = (a0 << 9) + b;
                unsigned ph = (a0 * (unsigned)x + b * (unsigned)y) & 511u;
                float cr, ci; __sincosf((float)ph * TH, &ci, &cr);
                #pragma unroll 4
                for (int q = 0; q < 8; q++) {
                    uint32_t hp[4], lp[4];
                    float m0 = 0.f;
                    #pragma unroll
                    for (int e = 0; e < 8; e++) {
                        float2 w = Wb[off];
                        float wsc = (b == 0u || b == 256u) ? 9.765625e-4f : 1.953125e-3f;
                        float mv = fmaf(w.x, cr, -w.y * ci) * wsc;
                        if ((e & 1) == 0) m0 = mv;
                        else {
                            __half h0 = __float2half_rn(m0);
                            __half h1 = __float2half_rn(mv);
                            float l0 = m0 - __half2float(h0);
                            float l1 = mv - __half2float(h1);
                            __half2 hh = __halves2half2(h0, h1);
                            __half2 ll = __halves2half2(__float2half_rn(l0), __float2half_rn(l1));
                            hp[e >> 1] = *reinterpret_cast<uint32_t*>(&hh);
                            lp[e >> 1] = *reinterpret_cast<uint32_t*>(&ll);
                        }
                        bool wrap = (b == 256u);
                        float fc = wrap ? cw : cy, fs = wrap ? sw_ : sy;
                        float nr = cr * fc - ci * fs;
                        float ni = fmaf(cr, fs, ci * fc);
                        cr = nr; ci = ni;
                        off += wrap ? 256u : 1u;
                        b = wrap ? 0u : b + 1u;
                    }
                    uint32_t da = st + (uint32_t)r * 128u + ((((uint32_t)q) ^ rx) << 4);
                    sts128(da, hp[0], hp[1], hp[2], hp[3]);
                    sts128(da + OFF_AL, lp[0], lp[1], lp[2], lp[3]);
                }
            }
            asm volatile("cp.async.wait_group 0;" ::: "memory");
            bar_arrive(1 + s);
        }
    } else {
        // ================= CONSUMER (12 warps = 4m x 3n, n=80) =================
        const int wm = wid & 3, wn = wid >> 2;       // wn 0..2
        const int mrow0 = wm * 32;
        const int n0 = wn * 80;
        const int lrowA = (lane & 7) + ((lane >> 3) & 1) * 8;
        const int lchA  = lane >> 4;
        const int lrowB = (lane & 7) + (lane >> 4) * 8;
        const int lchB  = (lane >> 3) & 1;

        float acc[2][10][4];
        #pragma unroll
        for (int s = 0; s < 2; s++)
            #pragma unroll
            for (int t8 = 0; t8 < 10; t8++)
                #pragma unroll
                for (int q = 0; q < 4; q++) acc[s][t8][q] = 0.f;

        for (int c = c0; c < c1; c++) {
            const int s3 = c % 3;
            bar_sync(1 + s3);
            const uint32_t st = sb + (uint32_t)s3 * STG_SZ;
            #pragma unroll
            for (int ks2 = 0; ks2 < 4; ks2++) {
                uint32_t Ah[2][4], Al[2][4];
                #pragma unroll
                for (int s = 0; s < 2; s++) {
                    int row = mrow0 + s * 16 + lrowA;
                    uint32_t a1 = st + (uint32_t)row * 128u
                                + ((((uint32_t)(ks2 * 2 + lchA)) ^ ((uint32_t)row & 7u)) << 4);
                    ldsm4(Ah[s], a1);
                    ldsm4(Al[s], a1 + OFF_AL);
                }
                #pragma unroll
                for (int jp = 0; jp < 5; jp++) {
                    int nr_ = n0 + jp * 16 + lrowB;
                    uint32_t ba = st + OFF_B + (uint32_t)nr_ * 128u
                                + ((((uint32_t)(ks2 * 2 + lchB)) ^ ((uint32_t)nr_ & 7u)) << 4);
                    uint32_t Bh[4];
                    ldsm4(Bh, ba);
                    // acc reuse distance 4
                    mma16816h(acc[0][2 * jp],     Ah[0], Bh);
                    mma16816h(acc[0][2 * jp + 1], Ah[0], Bh + 2);
                    mma16816h(acc[1][2 * jp],     Ah[1], Bh);
                    mma16816h(acc[1][2 * jp + 1], Ah[1], Bh + 2);
                    mma16816h(acc[0][2 * jp],     Al[0], Bh);
                    mma16816h(acc[0][2 * jp + 1], Al[0], Bh + 2);
                    mma16816h(acc[1][2 * jp],     Al[1], Bh);
                    mma16816h(acc[1][2 * jp + 1], Al[1], Bh + 2);
                }
            }
            bar_arrive(4 + s3);
        }

        // epilogue: write partials
        const int gq = lane >> 2, tg = lane & 3;
        #pragma unroll
        for (int s = 0; s < 2; s++) {
            const int rbase = mt * 128 + mrow0 + s * 16 + gq;
            #pragma unroll
            for (int t8 = 0; t8 < 10; t8++) {
                const int tt = n0 + t8 * 8 + tg * 2;
                float* d0 = g_Part + ((size_t)ks * 4096 + rbase) * NT + tt;
                *(float2*)d0 = make_float2(acc[s][t8][0], acc[s][t8][1]);
                float* d1 = d0 + 8 * NT;
                *(float2*)d1 = make_float2(acc[s][t8][2], acc[s][t8][3]);
            }
        }
    }
}

// ---------------- reduce over k-splits ----------------
__global__ void reduce_kernel(float* __restrict__ out)
{
    int i = blockIdx.x * 256 + threadIdx.x;   // i = row*240 + t
    if (i >= 4096 * NT) return;
    float s = 0.f;
    #pragma unroll
    for (int k = 0; k < KSP; k++) s += g_Part[(size_t)k * (4096 * NT) + i];
    out[i] = s;
}

extern "C" void kernel_launch(void* const* d_in, const int* in_sizes, int n_in,
                              void* d_out, int out_size)
{
    const float* f   = (const float*)d_in[0];
    const float* fil = (const float*)d_in[1];
    const int*  idx0 = (const int*)d_in[2];
    const int*  idx1 = (const int*)d_in[3];
    float* out = (float*)d_out;

    cudaFuncSetAttribute(gemm_kernel, cudaFuncAttributeMaxDynamicSharedMemorySize, SMEM_TOT);

    fft_rows_kernel<<<dim3(512, NB), 256>>>(f);
    fft_cols_kernel<<<dim3(512, NB), 256>>>();
    ggen_kernel<<<(KH + 255) / 256, 256>>>(fil);
    gemm_kernel<<<dim3(32, KSP), 512, SMEM_TOT>>>(idx0, idx1);
    reduce_kernel<<<(4096 * NT + 255) / 256, 256>>>(out);
}

// round 10
// speedup vs baseline: 1.6599x; 1.0011x over previous
#include <cuda_runtime.h>
#include <cuda_fp16.h>
#include <cuda_bf16.h>
#include <cstdint>

#define NB   16
#define NIN  256
#define NPHI 256
#define NT   240
#define KH   131584            // 512*257 Hermitian half
#define BK   64
#define NCH  (KH / BK)         // 2056
#define KSP  37                // 32*37 = 1184 = 8*148 exact waves
#define NS   3
#define OFF_AL 16384
#define OFF_B  32768
#define STG_SZ 63488           // A hi/lo 32KB + B 30KB
#define SMEM_TOT (NS * STG_SZ)

// ---------------- device scratch (static; no allocation) ----------------
__device__ float2         g_W[NB * 512 * 512];
__device__ unsigned short g_G1[(size_t)NT * KH];     // G fp16 (g * 2^-8), [t][kh]
__device__ float          g_Part[(size_t)KSP * 4096 * NT];

// ---------------- helpers ----------------
__device__ __forceinline__ uint32_t smem_u32(const void* p){
    uint32_t a; asm("{ .reg .u64 t; cvta.to.shared.u64 t, %1; cvt.u32.u64 %0, t; }":"=r"(a):"l"(p)); return a;
}
__device__ __forceinline__ void cp16(uint32_t dst, const void* src){
    asm volatile("cp.async.cg.shared.global [%0], [%1], 16;" :: "r"(dst), "l"(src) : "memory");
}
__device__ __forceinline__ void sts128(uint32_t a, uint32_t x, uint32_t y, uint32_t z, uint32_t w){
    asm volatile("st.shared.v4.b32 [%0], {%1,%2,%3,%4};" :: "r"(a), "r"(x), "r"(y), "r"(z), "r"(w) : "memory");
}
__device__ __forceinline__ void ldsm4(uint32_t* d, uint32_t a){
    asm volatile("ldmatrix.sync.aligned.m8n8.x4.shared.b16 {%0,%1,%2,%3}, [%4];"
        : "=r"(d[0]), "=r"(d[1]), "=r"(d[2]), "=r"(d[3]) : "r"(a));
}
__device__ __forceinline__ void mma16816h(float* c, const uint32_t* a, const uint32_t* b){
    asm volatile("mma.sync.aligned.m16n8k16.row.col.f32.f16.f16.f32 "
        "{%0,%1,%2,%3}, {%4,%5,%6,%7}, {%8,%9}, {%0,%1,%2,%3};"
        : "+f"(c[0]), "+f"(c[1]), "+f"(c[2]), "+f"(c[3])
        : "r"(a[0]), "r"(a[1]), "r"(a[2]), "r"(a[3]), "r"(b[0]), "r"(b[1]));
}
__device__ __forceinline__ void bar_sync(int id){
    asm volatile("bar.sync %0, 512;" :: "r"(id) : "memory");
}
__device__ __forceinline__ void bar_arrive(int id){
    asm volatile("bar.arrive %0, 512;" :: "r"(id) : "memory");
}

// ---------------- 512-pt radix-2 FFT (validated) ----------------
__device__ __forceinline__ void fft512(float2* buf, int tid, float sign)
{
    #pragma unroll
    for (int s = 0; s < 9; s++) {
        int half = 1 << s;
        int pos  = tid & (half - 1);
        int i0   = ((tid >> s) << (s + 1)) + pos;
        int i1   = i0 + half;
        float ang = sign * 3.14159265358979323846f * (float)pos / (float)half;
        float sv, cv;
        sincosf(ang, &sv, &cv);
        __syncthreads();
        float2 x0 = buf[i0], x1 = buf[i1];
        float tr = x1.x * cv - x1.y * sv;
        float ti = x1.x * sv + x1.y * cv;
        buf[i0] = make_float2(x0.x + tr, x0.y + ti);
        buf[i1] = make_float2(x0.x - tr, x0.y - ti);
    }
    __syncthreads();
}

__global__ void fft_rows_kernel(const float* __restrict__ f)
{
    int a = blockIdx.x, bb = blockIdx.y, tid = threadIdx.x;
    float2* wrow = g_W + ((size_t)bb << 18) + ((size_t)a << 9);
    if (a < 128 || a >= 384) {
        for (int i = tid; i < 512; i += 256) wrow[i] = make_float2(0.f, 0.f);
        return;
    }
    __shared__ float2 buf[512];
    const float* frow = f + (size_t)bb * (NIN * NIN) + (size_t)(a - 128) * NIN;
    for (int i = tid; i < 512; i += 256) {
        float v = (i >= 128 && i < 384) ? frow[i - 128] : 0.f;
        buf[__brev((unsigned)i) >> 23] = make_float2(v, 0.f);
    }
    fft512(buf, tid, -1.0f);
    for (int i = tid; i < 512; i += 256) wrow[i] = buf[i];
}

__global__ void fft_cols_kernel()
{
    int c = blockIdx.x, bb = blockIdx.y, tid = threadIdx.x;
    float2* base = g_W + ((size_t)bb << 18) + c;
    __shared__ float2 buf[512];
    for (int i = tid; i < 512; i += 256)
        buf[__brev((unsigned)i) >> 23] = base[(size_t)i << 9];
    fft512(buf, tid, -1.0f);
    for (int i = tid; i < 512; i += 256) base[(size_t)i << 9] = buf[i];
}

// ---------------- G table: fp16(g_{t+1} * 2^-8), [t][kh] ----------------
__global__ void ggen_kernel(const float* __restrict__ fil)
{
    int kh = blockIdx.x * 256 + threadIdx.x;
    if (kh >= KH) return;
    unsigned a = (unsigned)kh / 257u;
    unsigned b = (unsigned)kh - a * 257u;
    float c2 = 2.0f - 4.0f * fil[a * 512u + b];
    const float s8 = 0.00390625f;              // 2^-8
    float gp = s8;
    float gc = (c2 - 1.0f) * s8;
    #pragma unroll 4
    for (int t = 0; t < NT; t++) {
        __half h = __float2half_rn(gc);
        g_G1[(size_t)t * KH + kh] = *reinterpret_cast<unsigned short*>(&h);
        float gn = c2 * gc - gp;
        gp = gc; gc = gn;
    }
}

// ---------------- warp-specialized HMMA GEMM (fp16 2-pass, BK=64) ----------------
// 512 thr: warps 0-11 consumers (4m x 3n, n=80 each), warps 12-15 producers.
// B fragments double-buffered in registers to hide ldsm latency.
__global__ void __launch_bounds__(512, 1)
gemm_kernel(const int* __restrict__ idx0, const int* __restrict__ idx1)
{
    extern __shared__ char smem[];
    const uint32_t sb = smem_u32(smem);
    const int tid = threadIdx.x;
    const int wid = tid >> 5, lane = tid & 31;
    const int mt = blockIdx.x;       // 0..31
    const int ks = blockIdx.y;       // 0..36
    const int bb = mt >> 1;
    const int c0 = (ks * NCH) / KSP, c1 = ((ks + 1) * NCH) / KSP;

    if (wid >= 12) {
        // ================= PRODUCER (4 warps, 128 threads) =================
        const int r = tid - 384;                 // row 0..127
        const int p = ((mt & 1) << 7) + r;
        const int x = idx0[p], y = idx1[p];
        const float TH = 6.2831853071795864769e+00f / 512.0f;
        float cy, sy; sincosf((float)(((unsigned)y) & 511u) * TH, &sy, &cy);
        int wd = (x - 256 * y) % 512; if (wd < 0) wd += 512;
        float cw, sw_; sincosf((float)wd * TH, &sw_, &cw);
        const float2* Wb = g_W + ((size_t)bb << 18);
        const uint32_t rx = (uint32_t)r & 7u;

        for (int c = c0; c < c1; c++) {
            const int s = c % 3;
            if (c >= c0 + NS) bar_sync(4 + s);
            const uint32_t st = sb + (uint32_t)s * STG_SZ;
            const int k0 = c * BK;

            // B via cp.async: 1920 16B chunks over 128 threads (15 rounds)
            #pragma unroll
            for (int ii = 0; ii < 15; ii++) {
                int i = r + ii * 128;
                int n = i >> 3, cc = i & 7;
                uint32_t d = st + OFF_B + (uint32_t)n * 128u
                           + ((((uint32_t)cc) ^ ((uint32_t)n & 7u)) << 4);
                cp16(d, g_G1 + (size_t)n * KH + k0 + cc * 8);
            }
            asm volatile("cp.async.commit_group;" ::: "memory");

            // A-gen: 64 k-elems for row r; weight*2^-10 folded; fp16 hi + lo.
            {
                unsigned a0 = (unsigned)k0 / 257u;
                unsigned b  = (unsigned)k0 - a0 * 257u;
                unsigned off = (a0 << 9) + b;
                unsigned ph = (a0 * (unsigned)x + b * (unsigned)y) & 511u;
                float cr, ci; __sincosf((float)ph * TH, &ci, &cr);
                #pragma unroll 4
                for (int q = 0; q < 8; q++) {
                    uint32_t hp[4], lp[4];
                    float m0 = 0.f;
                    #pragma unroll
                    for (int e = 0; e < 8; e++) {
                        float2 w = Wb[off];
                        float wsc = (b == 0u || b == 256u) ? 9.765625e-4f : 1.953125e-3f;
                        float mv = fmaf(w.x, cr, -w.y * ci) * wsc;
                        if ((e & 1) == 0) m0 = mv;
                        else {
                            __half h0 = __float2half_rn(m0);
                            __half h1 = __float2half_rn(mv);
                            float l0 = m0 - __half2float(h0);
                            float l1 = mv - __half2float(h1);
                            __half2 hh = __halves2half2(h0, h1);
                            __half2 ll = __halves2half2(__float2half_rn(l0), __float2half_rn(l1));
                            hp[e >> 1] = *reinterpret_cast<uint32_t*>(&hh);
                            lp[e >> 1] = *reinterpret_cast<uint32_t*>(&ll);
                        }
                        bool wrap = (b == 256u);
                        float fc = wrap ? cw : cy, fs = wrap ? sw_ : sy;
                        float nr = cr * fc - ci * fs;
                        float ni = fmaf(cr, fs, ci * fc);
                        cr = nr; ci = ni;
                        off += wrap ? 256u : 1u;
                        b = wrap ? 0u : b + 1u;
                    }
                    uint32_t da = st + (uint32_t)r * 128u + ((((uint32_t)q) ^ rx) << 4);
                    sts128(da, hp[0], hp[1], hp[2], hp[3]);
                    sts128(da + OFF_AL, lp[0], lp[1], lp[2], lp[3]);
                }
            }
            asm volatile("cp.async.wait_group 0;" ::: "memory");
            bar_arrive(1 + s);
        }
    } else {
        // ================= CONSUMER (12 warps = 4m x 3n, n=80) =================
        const int wm = wid & 3, wn = wid >> 2;       // wn 0..2
        const int mrow0 = wm * 32;
        const int n0 = wn * 80;
        const int lrowA = (lane & 7) + ((lane >> 3) & 1) * 8;
        const int lchA  = lane >> 4;
        const int lrowB = (lane & 7) + (lane >> 4) * 8;
        const int lchB  = (lane >> 3) & 1;

        float acc[2][10][4];
        #pragma unroll
        for (int s = 0; s < 2; s++)
            #pragma unroll
            for (int t8 = 0; t8 < 10; t8++)
                #pragma unroll
                for (int q = 0; q < 4; q++) acc[s][t8][q] = 0.f;

        // B smem address for (ks2, jp)
        auto baddr = [&](uint32_t st, int ks2, int jp) -> uint32_t {
            int nr_ = n0 + jp * 16 + lrowB;
            return st + OFF_B + (uint32_t)nr_ * 128u
                 + ((((uint32_t)(ks2 * 2 + lchB)) ^ ((uint32_t)nr_ & 7u)) << 4);
        };

        for (int c = c0; c < c1; c++) {
            const int s3 = c % 3;
            bar_sync(1 + s3);
            const uint32_t st = sb + (uint32_t)s3 * STG_SZ;

            uint32_t Bcur[4], Bnxt[4];
            ldsm4(Bcur, baddr(st, 0, 0));        // prime B pipeline
            #pragma unroll
            for (int ks2 = 0; ks2 < 4; ks2++) {
                uint32_t Ah[2][4], Al[2][4];
                #pragma unroll
                for (int s = 0; s < 2; s++) {
                    int row = mrow0 + s * 16 + lrowA;
                    uint32_t a1 = st + (uint32_t)row * 128u
                                + ((((uint32_t)(ks2 * 2 + lchA)) ^ ((uint32_t)row & 7u)) << 4);
                    ldsm4(Ah[s], a1);
                    ldsm4(Al[s], a1 + OFF_AL);
                }
                #pragma unroll
                for (int jp = 0; jp < 5; jp++) {
                    // prefetch next B fragment before the mma group
                    if (jp < 4)            ldsm4(Bnxt, baddr(st, ks2, jp + 1));
                    else if (ks2 < 3)      ldsm4(Bnxt, baddr(st, ks2 + 1, 0));
                    // 8 mma on Bcur, acc reuse distance 4
                    mma16816h(acc[0][2 * jp],     Ah[0], Bcur);
                    mma16816h(acc[0][2 * jp + 1], Ah[0], Bcur + 2);
                    mma16816h(acc[1][2 * jp],     Ah[1], Bcur);
                    mma16816h(acc[1][2 * jp + 1], Ah[1], Bcur + 2);
                    mma16816h(acc[0][2 * jp],     Al[0], Bcur);
                    mma16816h(acc[0][2 * jp + 1], Al[0], Bcur + 2);
                    mma16816h(acc[1][2 * jp],     Al[1], Bcur);
                    mma16816h(acc[1][2 * jp + 1], Al[1], Bcur + 2);
                    #pragma unroll
                    for (int q = 0; q < 4; q++) Bcur[q] = Bnxt[q];
                }
            }
            bar_arrive(4 + s3);
        }

        // epilogue: write partials
        const int gq = lane >> 2, tg = lane & 3;
        #pragma unroll
        for (int s = 0; s < 2; s++) {
            const int rbase = mt * 128 + mrow0 + s * 16 + gq;
            #pragma unroll
            for (int t8 = 0; t8 < 10; t8++) {
                const int tt = n0 + t8 * 8 + tg * 2;
                float* d0 = g_Part + ((size_t)ks * 4096 + rbase) * NT + tt;
                *(float2*)d0 = make_float2(acc[s][t8][0], acc[s][t8][1]);
                float* d1 = d0 + 8 * NT;
                *(float2*)d1 = make_float2(acc[s][t8][2], acc[s][t8][3]);
            }
        }
    }
}

// ---------------- reduce over k-splits ----------------
__global__ void reduce_kernel(float* __restrict__ out)
{
    int i = blockIdx.x * 256 + threadIdx.x;   // i = row*240 + t
    if (i >= 4096 * NT) return;
    float s = 0.f;
    #pragma unroll
    for (int k = 0; k < KSP; k++) s += g_Part[(size_t)k * (4096 * NT) + i];
    out[i] = s;
}

extern "C" void kernel_launch(void* const* d_in, const int* in_sizes, int n_in,
                              void* d_out, int out_size)
{
    const float* f   = (const float*)d_in[0];
    const float* fil = (const float*)d_in[1];
    const int*  idx0 = (const int*)d_in[2];
    const int*  idx1 = (const int*)d_in[3];
    float* out = (float*)d_out;

    cudaFuncSetAttribute(gemm_kernel, cudaFuncAttributeMaxDynamicSharedMemorySize, SMEM_TOT);

    fft_rows_kernel<<<dim3(512, NB), 256>>>(f);
    fft_cols_kernel<<<dim3(512, NB), 256>>>();
    ggen_kernel<<<(KH + 255) / 256, 256>>>(fil);
    gemm_kernel<<<dim3(32, KSP), 512, SMEM_TOT>>>(idx0, idx1);
    reduce_kernel<<<(4096 * NT + 255) / 256, 256>>>(out);
}

// round 11
// speedup vs baseline: 1.7038x; 1.0265x over previous
#include <cuda_runtime.h>
#include <cuda_fp16.h>
#include <cuda_bf16.h>
#include <cstdint>

#define NB   16
#define NIN  256
#define NPHI 256
#define NT   240
#define KH   131584            // 512*257 Hermitian half
#define BK   64
#define NCH  (KH / BK)         // 2056
#define KSP  37                // 32*37 = 1184 CTAs
#define NS   4
#define OFF_B  16384
#define STG_SZ 47104           // A 16KB + B 30KB
#define SMEM_TOT (NS * STG_SZ)

// ---------------- device scratch (static; no allocation) ----------------
__device__ float2         g_W[NB * 512 * 512];
__device__ unsigned short g_G1[(size_t)NT * KH];     // G fp16 (g * 2^-8), [t][kh]
__device__ float          g_Part[(size_t)KSP * 4096 * NT];

// ---------------- helpers ----------------
__device__ __forceinline__ uint32_t smem_u32(const void* p){
    uint32_t a; asm("{ .reg .u64 t; cvta.to.shared.u64 t, %1; cvt.u32.u64 %0, t; }":"=r"(a):"l"(p)); return a;
}
__device__ __forceinline__ void cp16(uint32_t dst, const void* src){
    asm volatile("cp.async.cg.shared.global [%0], [%1], 16;" :: "r"(dst), "l"(src) : "memory");
}
__device__ __forceinline__ void sts128(uint32_t a, uint32_t x, uint32_t y, uint32_t z, uint32_t w){
    asm volatile("st.shared.v4.b32 [%0], {%1,%2,%3,%4};" :: "r"(a), "r"(x), "r"(y), "r"(z), "r"(w) : "memory");
}
__device__ __forceinline__ void ldsm4(uint32_t* d, uint32_t a){
    asm volatile("ldmatrix.sync.aligned.m8n8.x4.shared.b16 {%0,%1,%2,%3}, [%4];"
        : "=r"(d[0]), "=r"(d[1]), "=r"(d[2]), "=r"(d[3]) : "r"(a));
}
__device__ __forceinline__ void mma16816h(float* c, const uint32_t* a, const uint32_t* b){
    asm volatile("mma.sync.aligned.m16n8k16.row.col.f32.f16.f16.f32 "
        "{%0,%1,%2,%3}, {%4,%5,%6,%7}, {%8,%9}, {%0,%1,%2,%3};"
        : "+f"(c[0]), "+f"(c[1]), "+f"(c[2]), "+f"(c[3])
        : "r"(a[0]), "r"(a[1]), "r"(a[2]), "r"(a[3]), "r"(b[0]), "r"(b[1]));
}
__device__ __forceinline__ void bar_sync(int id){
    asm volatile("bar.sync %0, 512;" :: "r"(id) : "memory");
}
__device__ __forceinline__ void bar_arrive(int id){
    asm volatile("bar.arrive %0, 512;" :: "r"(id) : "memory");
}

// ---------------- 512-pt radix-2 FFT (validated) ----------------
__device__ __forceinline__ void fft512(float2* buf, int tid, float sign)
{
    #pragma unroll
    for (int s = 0; s < 9; s++) {
        int half = 1 << s;
        int pos  = tid & (half - 1);
        int i0   = ((tid >> s) << (s + 1)) + pos;
        int i1   = i0 + half;
        float ang = sign * 3.14159265358979323846f * (float)pos / (float)half;
        float sv, cv;
        sincosf(ang, &sv, &cv);
        __syncthreads();
        float2 x0 = buf[i0], x1 = buf[i1];
        float tr = x1.x * cv - x1.y * sv;
        float ti = x1.x * sv + x1.y * cv;
        buf[i0] = make_float2(x0.x + tr, x0.y + ti);
        buf[i1] = make_float2(x0.x - tr, x0.y - ti);
    }
    __syncthreads();
}

__global__ void fft_rows_kernel(const float* __restrict__ f)
{
    int a = blockIdx.x, bb = blockIdx.y, tid = threadIdx.x;
    float2* wrow = g_W + ((size_t)bb << 18) + ((size_t)a << 9);
    if (a < 128 || a >= 384) {
        for (int i = tid; i < 512; i += 256) wrow[i] = make_float2(0.f, 0.f);
        return;
    }
    __shared__ float2 buf[512];
    const float* frow = f + (size_t)bb * (NIN * NIN) + (size_t)(a - 128) * NIN;
    for (int i = tid; i < 512; i += 256) {
        float v = (i >= 128 && i < 384) ? frow[i - 128] : 0.f;
        buf[__brev((unsigned)i) >> 23] = make_float2(v, 0.f);
    }
    fft512(buf, tid, -1.0f);
    for (int i = tid; i < 512; i += 256) wrow[i] = buf[i];
}

__global__ void fft_cols_kernel()
{
    int c = blockIdx.x, bb = blockIdx.y, tid = threadIdx.x;
    float2* base = g_W + ((size_t)bb << 18) + c;
    __shared__ float2 buf[512];
    for (int i = tid; i < 512; i += 256)
        buf[__brev((unsigned)i) >> 23] = base[(size_t)i << 9];
    fft512(buf, tid, -1.0f);
    for (int i = tid; i < 512; i += 256) base[(size_t)i << 9] = buf[i];
}

// ---------------- G table: fp16(g_{t+1} * 2^-8), [t][kh] ----------------
__global__ void ggen_kernel(const float* __restrict__ fil)
{
    int kh = blockIdx.x * 256 + threadIdx.x;
    if (kh >= KH) return;
    unsigned a = (unsigned)kh / 257u;
    unsigned b = (unsigned)kh - a * 257u;
    float c2 = 2.0f - 4.0f * fil[a * 512u + b];
    const float s8 = 0.00390625f;              // 2^-8
    float gp = s8;
    float gc = (c2 - 1.0f) * s8;
    #pragma unroll 4
    for (int t = 0; t < NT; t++) {
        __half h = __float2half_rn(gc);
        g_G1[(size_t)t * KH + kh] = *reinterpret_cast<unsigned short*>(&h);
        float gn = c2 * gc - gp;
        gp = gc; gc = gn;
    }
}

// ---------------- warp-specialized HMMA GEMM (fp16 single-pass, BK=64) ----------------
// 512 thr: warps 0-11 consumers (4m x 3n, n=80 each), warps 12-15 producers.
__global__ void __launch_bounds__(512, 1)
gemm_kernel(const int* __restrict__ idx0, const int* __restrict__ idx1)
{
    extern __shared__ char smem[];
    const uint32_t sb = smem_u32(smem);
    const int tid = threadIdx.x;
    const int wid = tid >> 5, lane = tid & 31;
    const int mt = blockIdx.x;       // 0..31
    const int ks = blockIdx.y;       // 0..36
    const int bb = mt >> 1;
    const int c0 = (ks * NCH) / KSP, c1 = ((ks + 1) * NCH) / KSP;

    if (wid >= 12) {
        // ================= PRODUCER (4 warps, 128 threads) =================
        const int r = tid - 384;                 // row 0..127
        const int p = ((mt & 1) << 7) + r;
        const int x = idx0[p], y = idx1[p];
        const float TH = 6.2831853071795864769e+00f / 512.0f;
        float cy, sy; sincosf((float)(((unsigned)y) & 511u) * TH, &sy, &cy);
        int wd = (x - 256 * y) % 512; if (wd < 0) wd += 512;
        float cw, sw_; sincosf((float)wd * TH, &sw_, &cw);
        const float2* Wb = g_W + ((size_t)bb << 18);
        const uint32_t rx = (uint32_t)r & 7u;

        for (int c = c0; c < c1; c++) {
            const int s = c & (NS - 1);
            if (c >= c0 + NS) bar_sync(5 + s);
            const uint32_t st = sb + (uint32_t)s * STG_SZ;
            const int k0 = c * BK;

            // B via cp.async: 1920 16B chunks over 128 threads (15 rounds)
            #pragma unroll
            for (int ii = 0; ii < 15; ii++) {
                int i = r + ii * 128;
                int n = i >> 3, cc = i & 7;
                uint32_t d = st + OFF_B + (uint32_t)n * 128u
                           + ((((uint32_t)cc) ^ ((uint32_t)n & 7u)) << 4);
                cp16(d, g_G1 + (size_t)n * KH + k0 + cc * 8);
            }
            asm volatile("cp.async.commit_group;" ::: "memory");

            // A-gen: 64 k-elems for row r; weight*2^-10 folded; fp16 (single).
            {
                unsigned a0 = (unsigned)k0 / 257u;
                unsigned b  = (unsigned)k0 - a0 * 257u;
                unsigned off = (a0 << 9) + b;
                unsigned ph = (a0 * (unsigned)x + b * (unsigned)y) & 511u;
                float cr, ci; __sincosf((float)ph * TH, &ci, &cr);
                #pragma unroll 4
                for (int q = 0; q < 8; q++) {
                    uint32_t hp[4];
                    float m0 = 0.f;
                    #pragma unroll
                    for (int e = 0; e < 8; e++) {
                        float2 w = Wb[off];
                        float wsc = (b == 0u || b == 256u) ? 9.765625e-4f : 1.953125e-3f;
                        float mv = fmaf(w.x, cr, -w.y * ci) * wsc;
                        if ((e & 1) == 0) m0 = mv;
                        else {
                            __half2 hh = __halves2half2(__float2half_rn(m0), __float2half_rn(mv));
                            hp[e >> 1] = *reinterpret_cast<uint32_t*>(&hh);
                        }
                        bool wrap = (b == 256u);
                        float fc = wrap ? cw : cy, fs = wrap ? sw_ : sy;
                        float nr = cr * fc - ci * fs;
                        float ni = fmaf(cr, fs, ci * fc);
                        cr = nr; ci = ni;
                        off += wrap ? 256u : 1u;
                        b = wrap ? 0u : b + 1u;
                    }
                    uint32_t da = st + (uint32_t)r * 128u + ((((uint32_t)q) ^ rx) << 4);
                    sts128(da, hp[0], hp[1], hp[2], hp[3]);
                }
            }
            asm volatile("cp.async.wait_group 0;" ::: "memory");
            bar_arrive(1 + s);
        }
    } else {
        // ================= CONSUMER (12 warps = 4m x 3n, n=80) =================
        const int wm = wid & 3, wn = wid >> 2;       // wn 0..2
        const int mrow0 = wm * 32;
        const int n0 = wn * 80;
        const int lrowA = (lane & 7) + ((lane >> 3) & 1) * 8;
        const int lchA  = lane >> 4;
        const int lrowB = (lane & 7) + (lane >> 4) * 8;
        const int lchB  = (lane >> 3) & 1;

        float acc[2][10][4];
        #pragma unroll
        for (int s = 0; s < 2; s++)
            #pragma unroll
            for (int t8 = 0; t8 < 10; t8++)
                #pragma unroll
                for (int q = 0; q < 4; q++) acc[s][t8][q] = 0.f;

        // B smem address for (ks2, jp)
        auto baddr = [&](uint32_t st, int ks2, int jp) -> uint32_t {
            int nr_ = n0 + jp * 16 + lrowB;
            return st + OFF_B + (uint32_t)nr_ * 128u
                 + ((((uint32_t)(ks2 * 2 + lchB)) ^ ((uint32_t)nr_ & 7u)) << 4);
        };

        for (int c = c0; c < c1; c++) {
            const int s4 = c & (NS - 1);
            bar_sync(1 + s4);
            const uint32_t st = sb + (uint32_t)s4 * STG_SZ;

            uint32_t Bcur[4], Bnxt[4];
            ldsm4(Bcur, baddr(st, 0, 0));        // prime B pipeline
            #pragma unroll
            for (int ks2 = 0; ks2 < 4; ks2++) {
                uint32_t Ah[2][4];
                #pragma unroll
                for (int s = 0; s < 2; s++) {
                    int row = mrow0 + s * 16 + lrowA;
                    uint32_t a1 = st + (uint32_t)row * 128u
                                + ((((uint32_t)(ks2 * 2 + lchA)) ^ ((uint32_t)row & 7u)) << 4);
                    ldsm4(Ah[s], a1);
                }
                #pragma unroll
                for (int jp = 0; jp < 5; jp++) {
                    // prefetch next B fragment before the mma group
                    if (jp < 4)            ldsm4(Bnxt, baddr(st, ks2, jp + 1));
                    else if (ks2 < 3)      ldsm4(Bnxt, baddr(st, ks2 + 1, 0));
                    // 4 mma on Bcur, acc reuse distance 4
                    mma16816h(acc[0][2 * jp],     Ah[0], Bcur);
                    mma16816h(acc[0][2 * jp + 1], Ah[0], Bcur + 2);
                    mma16816h(acc[1][2 * jp],     Ah[1], Bcur);
                    mma16816h(acc[1][2 * jp + 1], Ah[1], Bcur + 2);
                    #pragma unroll
                    for (int q = 0; q < 4; q++) Bcur[q] = Bnxt[q];
                }
            }
            bar_arrive(5 + s4);
        }

        // epilogue: write partials
        const int gq = lane >> 2, tg = lane & 3;
        #pragma unroll
        for (int s = 0; s < 2; s++) {
            const int rbase = mt * 128 + mrow0 + s * 16 + gq;
            #pragma unroll
            for (int t8 = 0; t8 < 10; t8++) {
                const int tt = n0 + t8 * 8 + tg * 2;
                float* d0 = g_Part + ((size_t)ks * 4096 + rbase) * NT + tt;
                *(float2*)d0 = make_float2(acc[s][t8][0], acc[s][t8][1]);
                float* d1 = d0 + 8 * NT;
                *(float2*)d1 = make_float2(acc[s][t8][2], acc[s][t8][3]);
            }
        }
    }
}

// ---------------- reduce over k-splits ----------------
__global__ void reduce_kernel(float* __restrict__ out)
{
    int i = blockIdx.x * 256 + threadIdx.x;   // i = row*240 + t
    if (i >= 4096 * NT) return;
    float s = 0.f;
    #pragma unroll
    for (int k = 0; k < KSP; k++) s += g_Part[(size_t)k * (4096 * NT) + i];
    out[i] = s;
}

extern "C" void kernel_launch(void* const* d_in, const int* in_sizes, int n_in,
                              void* d_out, int out_size)
{
    const float* f   = (const float*)d_in[0];
    const float* fil = (const float*)d_in[1];
    const int*  idx0 = (const int*)d_in[2];
    const int*  idx1 = (const int*)d_in[3];
    float* out = (float*)d_out;

    cudaFuncSetAttribute(gemm_kernel, cudaFuncAttributeMaxDynamicSharedMemorySize, SMEM_TOT);

    fft_rows_kernel<<<dim3(512, NB), 256>>>(f);
    fft_cols_kernel<<<dim3(512, NB), 256>>>();
    ggen_kernel<<<(KH + 255) / 256, 256>>>(fil);
    gemm_kernel<<<dim3(32, KSP), 512, SMEM_TOT>>>(idx0, idx1);
    reduce_kernel<<<(4096 * NT + 255) / 256, 256>>>(out);
}

// round 12
// speedup vs baseline: 2.5388x; 1.4901x over previous
#include <cuda_runtime.h>
#include <cuda_fp16.h>
#include <cuda_bf16.h>
#include <cstdint>

#define NB   16
#define NIN  256
#define NPHI 256
#define NT   240
#define KH   131584            // 512*257 Hermitian half
#define BK   64
#define NCH  (KH / BK)         // 2056
#define KSP  37                // 32*37 = 1184 CTAs = 8*148 waves
#define NS   4
#define OFF_B    16384
#define STG_SZ   47104         // A 16KB + B 30KB
#define SM_LUT   0             // 512 * float2 = 4096 B
#define SM_WSL   4096          // 4 slots * 64 float2 = 2048 B
#define SM_STG   6144
#define SMEM_TOT (SM_STG + NS * STG_SZ)   // 194560

// ---------------- device scratch (static; no allocation) ----------------
__device__ float2         g_W[NB * 512 * 512];
__device__ unsigned short g_G1[(size_t)NT * KH];     // G fp16 (g * w * 2^-8), [t][kh]
__device__ float          g_Part[(size_t)KSP * 4096 * NT];

// ---------------- helpers ----------------
__device__ __forceinline__ uint32_t smem_u32(const void* p){
    uint32_t a; asm("{ .reg .u64 t; cvta.to.shared.u64 t, %1; cvt.u32.u64 %0, t; }":"=r"(a):"l"(p)); return a;
}
__device__ __forceinline__ void cp16(uint32_t dst, const void* src){
    asm volatile("cp.async.cg.shared.global [%0], [%1], 16;" :: "r"(dst), "l"(src) : "memory");
}
__device__ __forceinline__ void cp8(uint32_t dst, const void* src){
    asm volatile("cp.async.ca.shared.global [%0], [%1], 8;" :: "r"(dst), "l"(src) : "memory");
}
__device__ __forceinline__ void sts128(uint32_t a, uint32_t x, uint32_t y, uint32_t z, uint32_t w){
    asm volatile("st.shared.v4.b32 [%0], {%1,%2,%3,%4};" :: "r"(a), "r"(x), "r"(y), "r"(z), "r"(w) : "memory");
}
__device__ __forceinline__ void ldsm4(uint32_t* d, uint32_t a){
    asm volatile("ldmatrix.sync.aligned.m8n8.x4.shared.b16 {%0,%1,%2,%3}, [%4];"
        : "=r"(d[0]), "=r"(d[1]), "=r"(d[2]), "=r"(d[3]) : "r"(a));
}
__device__ __forceinline__ void mma16816h(float* c, const uint32_t* a, const uint32_t* b){
    asm volatile("mma.sync.aligned.m16n8k16.row.col.f32.f16.f16.f32 "
        "{%0,%1,%2,%3}, {%4,%5,%6,%7}, {%8,%9}, {%0,%1,%2,%3};"
        : "+f"(c[0]), "+f"(c[1]), "+f"(c[2]), "+f"(c[3])
        : "r"(a[0]), "r"(a[1]), "r"(a[2]), "r"(a[3]), "r"(b[0]), "r"(b[1]));
}
__device__ __forceinline__ void bar_sync(int id){
    asm volatile("bar.sync %0, 512;" :: "r"(id) : "memory");
}
__device__ __forceinline__ void bar_arrive(int id){
    asm volatile("bar.arrive %0, 512;" :: "r"(id) : "memory");
}
__device__ __forceinline__ void bar_sync_prod(){
    asm volatile("bar.sync 9, 128;" ::: "memory");
}

// ---------------- 512-pt radix-2 FFT (validated) ----------------
__device__ __forceinline__ void fft512(float2* buf, int tid, float sign)
{
    #pragma unroll
    for (int s = 0; s < 9; s++) {
        int half = 1 << s;
        int pos  = tid & (half - 1);
        int i0   = ((tid >> s) << (s + 1)) + pos;
        int i1   = i0 + half;
        float ang = sign * 3.14159265358979323846f * (float)pos / (float)half;
        float sv, cv;
        sincosf(ang, &sv, &cv);
        __syncthreads();
        float2 x0 = buf[i0], x1 = buf[i1];
        float tr = x1.x * cv - x1.y * sv;
        float ti = x1.x * sv + x1.y * cv;
        buf[i0] = make_float2(x0.x + tr, x0.y + ti);
        buf[i1] = make_float2(x0.x - tr, x0.y - ti);
    }
    __syncthreads();
}

__global__ void fft_rows_kernel(const float* __restrict__ f)
{
    int a = blockIdx.x, bb = blockIdx.y, tid = threadIdx.x;
    float2* wrow = g_W + ((size_t)bb << 18) + ((size_t)a << 9);
    if (a < 128 || a >= 384) {
        for (int i = tid; i < 512; i += 256) wrow[i] = make_float2(0.f, 0.f);
        return;
    }
    __shared__ float2 buf[512];
    const float* frow = f + (size_t)bb * (NIN * NIN) + (size_t)(a - 128) * NIN;
    for (int i = tid; i < 512; i += 256) {
        float v = (i >= 128 && i < 384) ? frow[i - 128] : 0.f;
        buf[__brev((unsigned)i) >> 23] = make_float2(v, 0.f);
    }
    fft512(buf, tid, -1.0f);
    for (int i = tid; i < 512; i += 256) wrow[i] = buf[i];
}

__global__ void fft_cols_kernel()
{
    int c = blockIdx.x, bb = blockIdx.y, tid = threadIdx.x;
    float2* base = g_W + ((size_t)bb << 18) + c;
    __shared__ float2 buf[512];
    for (int i = tid; i < 512; i += 256)
        buf[__brev((unsigned)i) >> 23] = base[(size_t)i << 9];
    fft512(buf, tid, -1.0f);
    for (int i = tid; i < 512; i += 256) base[(size_t)i << 9] = buf[i];
}

// ---------------- G table: fp16(g_{t+1} * w * 2^-8), [t][kh] ----------------
__global__ void ggen_kernel(const float* __restrict__ fil)
{
    int kh = blockIdx.x * 256 + threadIdx.x;
    if (kh >= KH) return;
    unsigned a = (unsigned)kh / 257u;
    unsigned b = (unsigned)kh - a * 257u;
    float c2 = 2.0f - 4.0f * fil[a * 512u + b];
    float w  = (b == 0u || b == 256u) ? 1.0f : 2.0f;
    float scale = w * 0.00390625f;              // w * 2^-8
    float gp = scale;
    float gc = (c2 - 1.0f) * scale;
    #pragma unroll 4
    for (int t = 0; t < NT; t++) {
        __half h = __float2half_rn(gc);
        g_G1[(size_t)t * KH + kh] = *reinterpret_cast<unsigned short*>(&h);
        float gn = c2 * gc - gp;
        gp = gc; gc = gn;
    }
}

// ---------------- warp-specialized HMMA GEMM (fp16, BK=64, LUT producer) ----------------
// 512 thr: warps 0-11 consumers (4m x 3n, n=80 each), warps 12-15 producers.
__global__ void __launch_bounds__(512, 1)
gemm_kernel(const int* __restrict__ idx0, const int* __restrict__ idx1)
{
    extern __shared__ char smem[];
    const uint32_t sb = smem_u32(smem);
    float2* lut = (float2*)smem;                      // [512]
    const int tid = threadIdx.x;
    const int wid = tid >> 5, lane = tid & 31;
    const int mt = blockIdx.x;       // 0..31
    const int ks = blockIdx.y;       // 0..36
    const int bb = mt >> 1;
    const int c0 = (ks * NCH) / KSP, c1 = ((ks + 1) * NCH) / KSP;

    // build (cos,sin)*2^-10 LUT, all threads
    {
        const float TH = 6.2831853071795864769e+00f / 512.0f;
        for (int i = tid; i < 512; i += 512) {
            float sv, cv; sincosf((float)i * TH, &sv, &cv);
            lut[i] = make_float2(cv * 9.765625e-4f, sv * 9.765625e-4f);
        }
    }
    __syncthreads();

    if (wid >= 12) {
        // ================= PRODUCER (4 warps, 128 threads) =================
        const int r = tid - 384;                 // row 0..127
        const int p = ((mt & 1) << 7) + r;
        const unsigned ux = (unsigned)idx0[p], uy = (unsigned)idx1[p];
        int wdi = ((int)ux - 256 * (int)uy) % 512; if (wdi < 0) wdi += 512;
        const unsigned wd = (unsigned)wdi;
        const float2* Wb = g_W + ((size_t)bb << 18);
        const uint32_t rx = (uint32_t)r & 7u;
        const uint32_t wbase = sb + SM_WSL;

        // prologue: W tile for chunk c0
        if (r < 64) {
            int kh = c0 * BK + r;
            unsigned a = (unsigned)kh / 257u, b2 = (unsigned)kh - a * 257u;
            cp8(wbase + (uint32_t)(c0 & 3) * 512u + (uint32_t)r * 8u, Wb + (a << 9) + b2);
        }
        asm volatile("cp.async.commit_group;" ::: "memory");
        asm volatile("cp.async.wait_group 0;" ::: "memory");
        bar_sync_prod();

        for (int c = c0; c < c1; c++) {
            const int s = c & (NS - 1);
            if (c >= c0 + NS) bar_sync(5 + s);
            const uint32_t st = sb + SM_STG + (uint32_t)s * STG_SZ;
            const int k0 = c * BK;

            // B via cp.async: 1920 16B chunks over 128 threads (15 rounds)
            #pragma unroll
            for (int ii = 0; ii < 15; ii++) {
                int i = r + ii * 128;
                int n = i >> 3, cc = i & 7;
                uint32_t d = st + OFF_B + (uint32_t)n * 128u
                           + ((((uint32_t)cc) ^ ((uint32_t)n & 7u)) << 4);
                cp16(d, g_G1 + (size_t)n * KH + k0 + cc * 8);
            }
            // W prefetch for chunk c+1
            if (r < 64 && c + 1 < NCH) {
                int kh = (c + 1) * BK + r;
                unsigned a = (unsigned)kh / 257u, b2 = (unsigned)kh - a * 257u;
                cp8(wbase + (uint32_t)((c + 1) & 3) * 512u + (uint32_t)r * 8u, Wb + (a << 9) + b2);
            }
            asm volatile("cp.async.commit_group;" ::: "memory");

            // A-gen: 64 k-elems for row r; integer phase + LUT; fp16.
            {
                const float2* wsm = (const float2*)(smem + SM_WSL + (c & 3) * 512);
                unsigned a0 = (unsigned)k0 / 257u;
                unsigned b  = (unsigned)k0 - a0 * 257u;
                unsigned ph = (a0 * ux + b * uy) & 511u;
                #pragma unroll
                for (int q = 0; q < 8; q++) {
                    uint32_t hp[4];
                    #pragma unroll
                    for (int h = 0; h < 4; h++) {
                        const int e = q * 8 + h * 2;
                        float2 w0 = wsm[e];
                        float2 cs0 = lut[ph];
                        float mv0 = w0.x * cs0.x - w0.y * cs0.y;
                        ph = (ph + ((b == 256u) ? wd : uy)) & 511u;
                        b  = (b == 256u) ? 0u : b + 1u;
                        float2 w1 = wsm[e + 1];
                        float2 cs1 = lut[ph];
                        float mv1 = w1.x * cs1.x - w1.y * cs1.y;
                        ph = (ph + ((b == 256u) ? wd : uy)) & 511u;
                        b  = (b == 256u) ? 0u : b + 1u;
                        __half2 hh = __halves2half2(__float2half_rn(mv0), __float2half_rn(mv1));
                        hp[h] = *reinterpret_cast<uint32_t*>(&hh);
                    }
                    uint32_t da = st + (uint32_t)r * 128u + ((((uint32_t)q) ^ rx) << 4);
                    sts128(da, hp[0], hp[1], hp[2], hp[3]);
                }
            }
            asm volatile("cp.async.wait_group 0;" ::: "memory");
            bar_sync_prod();           // W slot visibility among producers
            bar_arrive(1 + s);
        }
    } else {
        // ================= CONSUMER (12 warps = 4m x 3n, n=80) =================
        const int wm = wid & 3, wn = wid >> 2;       // wn 0..2
        const int mrow0 = wm * 32;
        const int n0 = wn * 80;
        const int lrowA = (lane & 7) + ((lane >> 3) & 1) * 8;
        const int lchA  = lane >> 4;
        const int lrowB = (lane & 7) + (lane >> 4) * 8;
        const int lchB  = (lane >> 3) & 1;

        float acc[2][10][4];
        #pragma unroll
        for (int s = 0; s < 2; s++)
            #pragma unroll
            for (int t8 = 0; t8 < 10; t8++)
                #pragma unroll
                for (int q = 0; q < 4; q++) acc[s][t8][q] = 0.f;

        auto baddr = [&](uint32_t st, int ks2, int jp) -> uint32_t {
            int nr_ = n0 + jp * 16 + lrowB;
            return st + OFF_B + (uint32_t)nr_ * 128u
                 + ((((uint32_t)(ks2 * 2 + lchB)) ^ ((uint32_t)nr_ & 7u)) << 4);
        };

        for (int c = c0; c < c1; c++) {
            const int s4 = c & (NS - 1);
            bar_sync(1 + s4);
            const uint32_t st = sb + SM_STG + (uint32_t)s4 * STG_SZ;

            uint32_t Bcur[4], Bnxt[4];
            ldsm4(Bcur, baddr(st, 0, 0));
            #pragma unroll
            for (int ks2 = 0; ks2 < 4; ks2++) {
                uint32_t Ah[2][4];
                #pragma unroll
                for (int s = 0; s < 2; s++) {
                    int row = mrow0 + s * 16 + lrowA;
                    uint32_t a1 = st + (uint32_t)row * 128u
                                + ((((uint32_t)(ks2 * 2 + lchA)) ^ ((uint32_t)row & 7u)) << 4);
                    ldsm4(Ah[s], a1);
                }
                #pragma unroll
                for (int jp = 0; jp < 5; jp++) {
                    if (jp < 4)            ldsm4(Bnxt, baddr(st, ks2, jp + 1));
                    else if (ks2 < 3)      ldsm4(Bnxt, baddr(st, ks2 + 1, 0));
                    mma16816h(acc[0][2 * jp],     Ah[0], Bcur);
                    mma16816h(acc[0][2 * jp + 1], Ah[0], Bcur + 2);
                    mma16816h(acc[1][2 * jp],     Ah[1], Bcur);
                    mma16816h(acc[1][2 * jp + 1], Ah[1], Bcur + 2);
                    #pragma unroll
                    for (int q = 0; q < 4; q++) Bcur[q] = Bnxt[q];
                }
            }
            bar_arrive(5 + s4);
        }

        // epilogue: write partials
        const int gq = lane >> 2, tg = lane & 3;
        #pragma unroll
        for (int s = 0; s < 2; s++) {
            const int rbase = mt * 128 + mrow0 + s * 16 + gq;
            #pragma unroll
            for (int t8 = 0; t8 < 10; t8++) {
                const int tt = n0 + t8 * 8 + tg * 2;
                float* d0 = g_Part + ((size_t)ks * 4096 + rbase) * NT + tt;
                *(float2*)d0 = make_float2(acc[s][t8][0], acc[s][t8][1]);
                float* d1 = d0 + 8 * NT;
                *(float2*)d1 = make_float2(acc[s][t8][2], acc[s][t8][3]);
            }
        }
    }
}

// ---------------- reduce over k-splits ----------------
__global__ void reduce_kernel(float* __restrict__ out)
{
    int i = blockIdx.x * 256 + threadIdx.x;   // i = row*240 + t
    if (i >= 4096 * NT) return;
    float s = 0.f;
    #pragma unroll
    for (int k = 0; k < KSP; k++) s += g_Part[(size_t)k * (4096 * NT) + i];
    out[i] = s;
}

extern "C" void kernel_launch(void* const* d_in, const int* in_sizes, int n_in,
                              void* d_out, int out_size)
{
    const float* f   = (const float*)d_in[0];
    const float* fil = (const float*)d_in[1];
    const int*  idx0 = (const int*)d_in[2];
    const int*  idx1 = (const int*)d_in[3];
    float* out = (float*)d_out;

    cudaFuncSetAttribute(gemm_kernel, cudaFuncAttributeMaxDynamicSharedMemorySize, SMEM_TOT);

    fft_rows_kernel<<<dim3(512, NB), 256>>>(f);
    fft_cols_kernel<<<dim3(512, NB), 256>>>();
    ggen_kernel<<<(KH + 255) / 256, 256>>>(fil);
    gemm_kernel<<<dim3(32, KSP), 512, SMEM_TOT>>>(idx0, idx1);
    reduce_kernel<<<(4096 * NT + 255) / 256, 256>>>(out);
}

// round 13
// speedup vs baseline: 3.0059x; 1.1840x over previous
#include <cuda_runtime.h>
#include <cuda_fp16.h>
#include <cuda_bf16.h>
#include <cstdint>

#define NB   16
#define NIN  256
#define NPHI 256
#define NT   240
#define KH   131584            // 512*257 Hermitian half
#define BK   64
#define NCH  (KH / BK)         // 2056
#define KSP  37                // 32*37 = 1184 CTAs = 8*148 waves
#define NS   4
#define OFF_B    16384
#define STG_SZ   47104         // A 16KB + B 30KB
#define SM_WSL   0             // 4 slots * 64 float2 = 2048 B
#define SM_STG   2048
#define SMEM_TOT (SM_STG + NS * STG_SZ)   // 190464

// ---------------- device scratch (static; no allocation) ----------------
__device__ float2         g_W[NB * 512 * 512];
__device__ unsigned short g_G1[(size_t)NT * KH];     // G fp16 (g * w * 2^-8), [t][kh]
__device__ float          g_Part[(size_t)KSP * 4096 * NT];

// ---------------- helpers ----------------
__device__ __forceinline__ uint32_t smem_u32(const void* p){
    uint32_t a; asm("{ .reg .u64 t; cvta.to.shared.u64 t, %1; cvt.u32.u64 %0, t; }":"=r"(a):"l"(p)); return a;
}
__device__ __forceinline__ void cp16(uint32_t dst, const void* src){
    asm volatile("cp.async.cg.shared.global [%0], [%1], 16;" :: "r"(dst), "l"(src) : "memory");
}
__device__ __forceinline__ void cp8(uint32_t dst, const void* src){
    asm volatile("cp.async.ca.shared.global [%0], [%1], 8;" :: "r"(dst), "l"(src) : "memory");
}
__device__ __forceinline__ void sts128(uint32_t a, uint32_t x, uint32_t y, uint32_t z, uint32_t w){
    asm volatile("st.shared.v4.b32 [%0], {%1,%2,%3,%4};" :: "r"(a), "r"(x), "r"(y), "r"(z), "r"(w) : "memory");
}
__device__ __forceinline__ void ldsm4(uint32_t* d, uint32_t a){
    asm volatile("ldmatrix.sync.aligned.m8n8.x4.shared.b16 {%0,%1,%2,%3}, [%4];"
        : "=r"(d[0]), "=r"(d[1]), "=r"(d[2]), "=r"(d[3]) : "r"(a));
}
__device__ __forceinline__ void mma16816h(float* c, const uint32_t* a, const uint32_t* b){
    asm volatile("mma.sync.aligned.m16n8k16.row.col.f32.f16.f16.f32 "
        "{%0,%1,%2,%3}, {%4,%5,%6,%7}, {%8,%9}, {%0,%1,%2,%3};"
        : "+f"(c[0]), "+f"(c[1]), "+f"(c[2]), "+f"(c[3])
        : "r"(a[0]), "r"(a[1]), "r"(a[2]), "r"(a[3]), "r"(b[0]), "r"(b[1]));
}
__device__ __forceinline__ void bar_sync(int id){
    asm volatile("bar.sync %0, 512;" :: "r"(id) : "memory");
}
__device__ __forceinline__ void bar_arrive(int id){
    asm volatile("bar.arrive %0, 512;" :: "r"(id) : "memory");
}
__device__ __forceinline__ void bar_sync_prod(){
    asm volatile("bar.sync 9, 128;" ::: "memory");
}

// ---------------- 512-pt radix-2 FFT (validated) ----------------
__device__ __forceinline__ void fft512(float2* buf, int tid, float sign)
{
    #pragma unroll
    for (int s = 0; s < 9; s++) {
        int half = 1 << s;
        int pos  = tid & (half - 1);
        int i0   = ((tid >> s) << (s + 1)) + pos;
        int i1   = i0 + half;
        float ang = sign * 3.14159265358979323846f * (float)pos / (float)half;
        float sv, cv;
        sincosf(ang, &sv, &cv);
        __syncthreads();
        float2 x0 = buf[i0], x1 = buf[i1];
        float tr = x1.x * cv - x1.y * sv;
        float ti = x1.x * sv + x1.y * cv;
        buf[i0] = make_float2(x0.x + tr, x0.y + ti);
        buf[i1] = make_float2(x0.x - tr, x0.y - ti);
    }
    __syncthreads();
}

__global__ void fft_rows_kernel(const float* __restrict__ f)
{
    int a = blockIdx.x, bb = blockIdx.y, tid = threadIdx.x;
    float2* wrow = g_W + ((size_t)bb << 18) + ((size_t)a << 9);
    if (a < 128 || a >= 384) {
        for (int i = tid; i < 512; i += 256) wrow[i] = make_float2(0.f, 0.f);
        return;
    }
    __shared__ float2 buf[512];
    const float* frow = f + (size_t)bb * (NIN * NIN) + (size_t)(a - 128) * NIN;
    for (int i = tid; i < 512; i += 256) {
        float v = (i >= 128 && i < 384) ? frow[i - 128] : 0.f;
        buf[__brev((unsigned)i) >> 23] = make_float2(v, 0.f);
    }
    fft512(buf, tid, -1.0f);
    for (int i = tid; i < 512; i += 256) wrow[i] = buf[i];
}

__global__ void fft_cols_kernel()
{
    int c = blockIdx.x, bb = blockIdx.y, tid = threadIdx.x;
    float2* base = g_W + ((size_t)bb << 18) + c;
    __shared__ float2 buf[512];
    for (int i = tid; i < 512; i += 256)
        buf[__brev((unsigned)i) >> 23] = base[(size_t)i << 9];
    fft512(buf, tid, -1.0f);
    for (int i = tid; i < 512; i += 256) base[(size_t)i << 9] = buf[i];
}

// ---------------- G table: fp16(g_{t+1} * w * 2^-8), [t][kh] ----------------
__global__ void ggen_kernel(const float* __restrict__ fil)
{
    int kh = blockIdx.x * 256 + threadIdx.x;
    if (kh >= KH) return;
    unsigned a = (unsigned)kh / 257u;
    unsigned b = (unsigned)kh - a * 257u;
    float c2 = 2.0f - 4.0f * fil[a * 512u + b];
    float w  = (b == 0u || b == 256u) ? 1.0f : 2.0f;
    float scale = w * 0.00390625f;              // w * 2^-8
    float gp = scale;
    float gc = (c2 - 1.0f) * scale;
    #pragma unroll 4
    for (int t = 0; t < NT; t++) {
        __half h = __float2half_rn(gc);
        g_G1[(size_t)t * KH + kh] = *reinterpret_cast<unsigned short*>(&h);
        float gn = c2 * gc - gp;
        gp = gc; gc = gn;
    }
}

// ---------------- warp-specialized HMMA GEMM (fp16, BK=64, rotation producer) ----------------
// 512 thr: warps 0-11 consumers (4m x 3n, n=80 each), warps 12-15 producers.
__global__ void __launch_bounds__(512, 1)
gemm_kernel(const int* __restrict__ idx0, const int* __restrict__ idx1)
{
    extern __shared__ char smem[];
    const uint32_t sb = smem_u32(smem);
    const int tid = threadIdx.x;
    const int wid = tid >> 5, lane = tid & 31;
    const int mt = blockIdx.x;       // 0..31
    const int ks = blockIdx.y;       // 0..36
    const int bb = mt >> 1;
    const int c0 = (ks * NCH) / KSP, c1 = ((ks + 1) * NCH) / KSP;

    if (wid >= 12) {
        // ================= PRODUCER (4 warps, 128 threads) =================
        const int r = tid - 384;                 // row 0..127
        const int p = ((mt & 1) << 7) + r;
        const unsigned ux = (unsigned)idx0[p], uy = (unsigned)idx1[p];
        int wdi = ((int)ux - 256 * (int)uy) % 512; if (wdi < 0) wdi += 512;
        const unsigned wd = (unsigned)wdi;
        const float TH = 6.2831853071795864769e+00f / 512.0f;
        float cy, sy; sincosf((float)(uy & 511u) * TH, &sy, &cy);
        float cw, sw_; sincosf((float)wd * TH, &sw_, &cw);
        const float2* Wb = g_W + ((size_t)bb << 18);
        const uint32_t rx = (uint32_t)r & 7u;
        const uint32_t wbase = sb + SM_WSL;

        // prologue: W tile for chunk c0
        if (r < 64) {
            int kh = c0 * BK + r;
            unsigned a = (unsigned)kh / 257u, b2 = (unsigned)kh - a * 257u;
            cp8(wbase + (uint32_t)(c0 & 3) * 512u + (uint32_t)r * 8u, Wb + (a << 9) + b2);
        }
        asm volatile("cp.async.commit_group;" ::: "memory");
        asm volatile("cp.async.wait_group 0;" ::: "memory");
        bar_sync_prod();

        for (int c = c0; c < c1; c++) {
            const int s = c & (NS - 1);
            if (c >= c0 + NS) bar_sync(5 + s);
            const uint32_t st = sb + SM_STG + (uint32_t)s * STG_SZ;
            const int k0 = c * BK;

            // B via cp.async: 1920 16B chunks over 128 threads (15 rounds)
            #pragma unroll
            for (int ii = 0; ii < 15; ii++) {
                int i = r + ii * 128;
                int n = i >> 3, cc = i & 7;
                uint32_t d = st + OFF_B + (uint32_t)n * 128u
                           + ((((uint32_t)cc) ^ ((uint32_t)n & 7u)) << 4);
                cp16(d, g_G1 + (size_t)n * KH + k0 + cc * 8);
            }
            // W prefetch for chunk c+1
            if (r < 64 && c + 1 < NCH) {
                int kh = (c + 1) * BK + r;
                unsigned a = (unsigned)kh / 257u, b2 = (unsigned)kh - a * 257u;
                cp8(wbase + (uint32_t)((c + 1) & 3) * 512u + (uint32_t)r * 8u, Wb + (a << 9) + b2);
            }
            asm volatile("cp.async.commit_group;" ::: "memory");

            // A-gen: 64 k-elems for row r; register complex rotation; fp16.
            {
                const float2* wsm = (const float2*)(smem + SM_WSL + (c & 3) * 512);
                unsigned a0 = (unsigned)k0 / 257u;
                unsigned b  = (unsigned)k0 - a0 * 257u;
                unsigned ph = (a0 * ux + b * uy) & 511u;
                float cr, ci; __sincosf((float)ph * TH, &ci, &cr);
                cr *= 9.765625e-4f; ci *= 9.765625e-4f;      // fold 2^-10
                #pragma unroll
                for (int q = 0; q < 8; q++) {
                    uint32_t hp[4];
                    #pragma unroll
                    for (int h = 0; h < 4; h++) {
                        const int e = q * 8 + h * 2;
                        float2 w0 = wsm[e];
                        float mv0 = w0.x * cr - w0.y * ci;
                        {
                            bool wrap = (b == 256u);
                            float fc = wrap ? cw : cy, fs = wrap ? sw_ : sy;
                            float nr = cr * fc - ci * fs;
                            float ni = fmaf(cr, fs, ci * fc);
                            cr = nr; ci = ni;
                            b = wrap ? 0u : b + 1u;
                        }
                        float2 w1 = wsm[e + 1];
                        float mv1 = w1.x * cr - w1.y * ci;
                        {
                            bool wrap = (b == 256u);
                            float fc = wrap ? cw : cy, fs = wrap ? sw_ : sy;
                            float nr = cr * fc - ci * fs;
                            float ni = fmaf(cr, fs, ci * fc);
                            cr = nr; ci = ni;
                            b = wrap ? 0u : b + 1u;
                        }
                        __half2 hh = __halves2half2(__float2half_rn(mv0), __float2half_rn(mv1));
                        hp[h] = *reinterpret_cast<uint32_t*>(&hh);
                    }
                    uint32_t da = st + (uint32_t)r * 128u + ((((uint32_t)q) ^ rx) << 4);
                    sts128(da, hp[0], hp[1], hp[2], hp[3]);
                }
            }
            asm volatile("cp.async.wait_group 0;" ::: "memory");
            bar_sync_prod();           // W slot visibility among producers
            bar_arrive(1 + s);
        }
    } else {
        // ================= CONSUMER (12 warps = 4m x 3n, n=80) =================
        const int wm = wid & 3, wn = wid >> 2;       // wn 0..2
        const int mrow0 = wm * 32;
        const int n0 = wn * 80;
        const int lrowA = (lane & 7) + ((lane >> 3) & 1) * 8;
        const int lchA  = lane >> 4;
        const int lrowB = (lane & 7) + (lane >> 4) * 8;
        const int lchB  = (lane >> 3) & 1;

        float acc[2][10][4];
        #pragma unroll
        for (int s = 0; s < 2; s++)
            #pragma unroll
            for (int t8 = 0; t8 < 10; t8++)
                #pragma unroll
                for (int q = 0; q < 4; q++) acc[s][t8][q] = 0.f;

        auto baddr = [&](uint32_t st, int ks2, int jp) -> uint32_t {
            int nr_ = n0 + jp * 16 + lrowB;
            return st + OFF_B + (uint32_t)nr_ * 128u
                 + ((((uint32_t)(ks2 * 2 + lchB)) ^ ((uint32_t)nr_ & 7u)) << 4);
        };

        for (int c = c0; c < c1; c++) {
            const int s4 = c & (NS - 1);
            bar_sync(1 + s4);
            const uint32_t st = sb + SM_STG + (uint32_t)s4 * STG_SZ;

            uint32_t Bcur[4], Bnxt[4];
            ldsm4(Bcur, baddr(st, 0, 0));
            #pragma unroll
            for (int ks2 = 0; ks2 < 4; ks2++) {
                uint32_t Ah[2][4];
                #pragma unroll
                for (int s = 0; s < 2; s++) {
                    int row = mrow0 + s * 16 + lrowA;
                    uint32_t a1 = st + (uint32_t)row * 128u
                                + ((((uint32_t)(ks2 * 2 + lchA)) ^ ((uint32_t)row & 7u)) << 4);
                    ldsm4(Ah[s], a1);
                }
                #pragma unroll
                for (int jp = 0; jp < 5; jp++) {
                    if (jp < 4)            ldsm4(Bnxt, baddr(st, ks2, jp + 1));
                    else if (ks2 < 3)      ldsm4(Bnxt, baddr(st, ks2 + 1, 0));
                    mma16816h(acc[0][2 * jp],     Ah[0], Bcur);
                    mma16816h(acc[0][2 * jp + 1], Ah[0], Bcur + 2);
                    mma16816h(acc[1][2 * jp],     Ah[1], Bcur);
                    mma16816h(acc[1][2 * jp + 1], Ah[1], Bcur + 2);
                    #pragma unroll
                    for (int q = 0; q < 4; q++) Bcur[q] = Bnxt[q];
                }
            }
            bar_arrive(5 + s4);
        }

        // epilogue: write partials
        const int gq = lane >> 2, tg = lane & 3;
        #pragma unroll
        for (int s = 0; s < 2; s++) {
            const int rbase = mt * 128 + mrow0 + s * 16 + gq;
            #pragma unroll
            for (int t8 = 0; t8 < 10; t8++) {
                const int tt = n0 + t8 * 8 + tg * 2;
                float* d0 = g_Part + ((size_t)ks * 4096 + rbase) * NT + tt;
                *(float2*)d0 = make_float2(acc[s][t8][0], acc[s][t8][1]);
                float* d1 = d0 + 8 * NT;
                *(float2*)d1 = make_float2(acc[s][t8][2], acc[s][t8][3]);
            }
        }
    }
}

// ---------------- reduce over k-splits ----------------
__global__ void reduce_kernel(float* __restrict__ out)
{
    int i = blockIdx.x * 256 + threadIdx.x;   // i = row*240 + t
    if (i >= 4096 * NT) return;
    float s = 0.f;
    #pragma unroll
    for (int k = 0; k < KSP; k++) s += g_Part[(size_t)k * (4096 * NT) + i];
    out[i] = s;
}

extern "C" void kernel_launch(void* const* d_in, const int* in_sizes, int n_in,
                              void* d_out, int out_size)
{
    const float* f   = (const float*)d_in[0];
    const float* fil = (const float*)d_in[1];
    const int*  idx0 = (const int*)d_in[2];
    const int*  idx1 = (const int*)d_in[3];
    float* out = (float*)d_out;

    cudaFuncSetAttribute(gemm_kernel, cudaFuncAttributeMaxDynamicSharedMemorySize, SMEM_TOT);

    fft_rows_kernel<<<dim3(512, NB), 256>>>(f);
    fft_cols_kernel<<<dim3(512, NB), 256>>>();
    ggen_kernel<<<(KH + 255) / 256, 256>>>(fil);
    gemm_kernel<<<dim3(32, KSP), 512, SMEM_TOT>>>(idx0, idx1);
    reduce_kernel<<<(4096 * NT + 255) / 256, 256>>>(out);
}